// round 12
// baseline (speedup 1.0000x reference)
#include <cuda_runtime.h>
#include <math.h>
#include <stdint.h>

// ---------------- problem constants ----------------
#define CU   256
#define CL   128
#define CB   512
#define CNR  65024               // CB*(CL-1)
#define CH   1024                // 4*U

static constexpr float LR = 0.01f;
static constexpr float DREC_SCALE = 2.0f / (65024.0f * 256.0f);

// ---------------- scratch ----------------
static constexpr size_t SZ_NU = (size_t)CNR * CU;
static constexpr size_t SZ_NH = (size_t)CNR * CH;

static constexpr size_t O_Z      = 0;
static constexpr size_t O_REC    = O_Z   + SZ_NU;
static constexpr size_t O_DZ     = O_REC + SZ_NU;
static constexpr size_t O_PRE    = O_DZ  + SZ_NU;   // dgelu(pre), then dpre in-place
static constexpr size_t O_H      = O_PRE + SZ_NH;
static constexpr size_t O_XR     = O_H   + SZ_NH;                 // rounded X [CNR,256]
static constexpr size_t O_DW1T   = O_XR  + SZ_NU;                 // [1024,256]
static constexpr size_t O_DW2T   = O_DW1T + (size_t)CH*CU;        // [256,1024]
static constexpr size_t O_DB1    = O_DW2T + (size_t)CU*CH;
static constexpr size_t O_DB2    = O_DB1 + CH;                    // contiguous zero range end
static constexpr size_t O_WPT    = O_DB2 + CU;                    // [256,128]
static constexpr size_t O_WPHIT  = O_WPT + (size_t)CU*128;        // [256,256]
static constexpr size_t O_W1T    = O_WPHIT + (size_t)CU*CU;       // [1024,256]
static constexpr size_t O_W2T    = O_W1T + (size_t)CH*CU;         // [256,1024]
static constexpr size_t O_WGT    = O_W2T + (size_t)CU*CH;
static constexpr size_t O_WPSIT  = O_WGT + (size_t)CU*CU;
static constexpr size_t O_WHT    = O_WPSIT + (size_t)CU*CU;
static constexpr size_t O_WGR    = O_WHT + (size_t)CU*CU;
static constexpr size_t O_W2R    = O_WGR + (size_t)CU*CU;         // [1024,256]
static constexpr size_t O_WPHIR  = O_W2R + (size_t)CH*CU;         // rounded Wphi [256,256]
static constexpr size_t O_WPW1T  = O_WPHIR + (size_t)CU*CU;       // (Wphi@W1)^T [1024,256]
static constexpr size_t O_COMBT  = O_WPW1T + (size_t)CH*CU;       // (W2@Wg)^T [256,1024]
static constexpr size_t O_COMB   = O_COMBT + (size_t)CU*CH;       // W2@Wg [1024,256]
static constexpr size_t O_GT     = O_COMB + (size_t)CH*CU;        // H^T@dz [1024,256]
static constexpr size_t O_GX     = O_GT + (size_t)CH*CU;          // dpre^T@XR [1024,256]
static constexpr size_t O_CDZ    = O_GX + (size_t)CH*CU;          // [256] (GT,GX,CDZ zero range)
static constexpr size_t O_ZB     = O_CDZ + CU;
static constexpr size_t O_ZB2    = O_ZB + CU;                     // [1024]
static constexpr size_t O_INR    = O_ZB2 + CH;                    // rounded inputs [512,128]
static constexpr size_t O_PROJ   = O_INR + (size_t)CB*128;
static constexpr size_t O_PROJR  = O_PROJ + (size_t)CB*CU;
static constexpr size_t O_PSI    = O_PROJR + (size_t)CB*CU;
static constexpr size_t O_HPSI   = O_PSI  + (size_t)CB*CU;
static constexpr size_t O_EPSIC  = O_HPSI + (size_t)CB*CH;
static constexpr size_t O_CONTRIB= O_EPSIC + (size_t)CB*CU;
static constexpr size_t O_W1C    = O_CONTRIB + (size_t)CB*CU;     // [1024,256]
static constexpr size_t O_W2C    = O_W1C + (size_t)CH*CU;         // [256,1024]
static constexpr size_t O_B1C    = O_W2C + (size_t)CU*CH;
static constexpr size_t O_B2C    = O_B1C + CH;
static constexpr size_t O_END    = O_B2C + CU;

__device__ float g_scratch[O_END];

// ---------------- helpers ----------------
__device__ __forceinline__ float gelu_f(float x) {
    return 0.5f * x * (1.0f + erff(x * 0.7071067811865476f));
}
__device__ __forceinline__ void gelu_both(float x, float& gv, float& dv) {
    float cdf = 0.5f * (1.0f + erff(x * 0.7071067811865476f));
    gv = x * cdf;
    dv = cdf + x * 0.3989422804014327f * expf(-0.5f * x * x);
}
__device__ __forceinline__ uint32_t f2tf(float x) {
    uint32_t r; asm("cvt.rna.tf32.f32 %0, %1;" : "=r"(r) : "f"(x)); return r;
}
__device__ __forceinline__ float roundtf(float x) { return __uint_as_float(f2tf(x)); }

#define LDSM4(r0,r1,r2,r3,addr) \
    asm volatile("ldmatrix.sync.aligned.m8n8.x4.shared.b16 {%0,%1,%2,%3}, [%4];" \
                 : "=r"(r0),"=r"(r1),"=r"(r2),"=r"(r3) : "r"(addr))

#define MMA_TF32(c,a0,a1,a2,a3,b0,b1) \
    asm volatile("mma.sync.aligned.m16n8k8.row.col.f32.tf32.tf32.f32 " \
                 "{%0,%1,%2,%3},{%4,%5,%6,%7},{%8,%9},{%0,%1,%2,%3};" \
                 : "+f"(c[0]),"+f"(c[1]),"+f"(c[2]),"+f"(c[3]) \
                 : "r"(a0),"r"(a1),"r"(a2),"r"(a3),"r"(b0),"r"(b1))

#define CP16(smaddr, gptr) \
    asm volatile("cp.async.cg.shared.global [%0], [%1], 16;" :: "r"(smaddr), "l"(gptr))

// ================= FAST NN GEMM (8-warp, cp.async 4-stage, 1 barrier/chunk) =================
// modes: 0 bias; 1 Caux=dgelu(pre), C=gelu(pre); 2 C*=aux; 3 C=gelu; 4 C+=aux (elementwise)
static constexpr int FSTRIDE = 36;
static constexpr int FA_STAGE = 128 * FSTRIDE;
static constexpr int FB_STAGE = 256 * FSTRIDE;
static constexpr int STAGE_W  = FA_STAGE + FB_STAGE;
static constexpr int FAST_SMEM_BYTES = 4 * STAGE_W * 4;           // 221184 B

__global__ void __launch_bounds__(256, 1) gemm_nn_fast(
    const float* __restrict__ A, const float* __restrict__ BT,
    const float* __restrict__ bias,
    float* __restrict__ C, float* __restrict__ Caux, const float* __restrict__ aux,
    float* __restrict__ colsum_out,
    int K, int lda, int ldbt, int ldc, int mode, int roundC)
{
    extern __shared__ uint32_t sm[];
    const int tid = threadIdx.x, lane = tid & 31, wid = tid >> 5;
    const int wm = wid & 1, wn = wid >> 1;
    const int g = lane >> 2, tig = lane & 3;
    const int bm = blockIdx.y * 128, bn = blockIdx.x * 256;

    float acc[4][8][4] = {};

    const uint32_t smBase = (uint32_t)__cvta_generic_to_shared(sm);
    const int aRow = (wm * 64 + (lane & 15)) * FSTRIDE + ((lane & 16) ? 4 : 0);
    const int bRow = FA_STAGE + (wn * 64 + (lane & 7) + ((lane & 16) ? 8 : 0)) * FSTRIDE
                   + ((lane & 8) ? 4 : 0);

    const int nch = K / 32;

    auto issueStage = [&](int ci) {
        const int st = ci & 3;
        uint32_t sa = smBase + (uint32_t)(st * STAGE_W * 4);
        const int k0 = ci * 32;
        #pragma unroll
        for (int t = 0; t < 4; t++) {
            int id = t * 256 + tid;
            int row = id >> 3, kc = (id & 7) << 2;
            uint32_t d = sa + (uint32_t)((row * FSTRIDE + kc) << 2);
            CP16(d, A + (size_t)(bm + row) * lda + k0 + kc);
        }
        uint32_t sb = sa + (uint32_t)(FA_STAGE * 4);
        #pragma unroll
        for (int t = 0; t < 8; t++) {
            int id = t * 256 + tid;
            int row = id >> 3, kc = (id & 7) << 2;
            uint32_t d = sb + (uint32_t)((row * FSTRIDE + kc) << 2);
            CP16(d, BT + (size_t)(bn + row) * ldbt + k0 + kc);
        }
        asm volatile("cp.async.commit_group;");
    };

    issueStage(0);
    if (nch > 1) issueStage(1);
    if (nch > 2) issueStage(2);

    for (int ci = 0; ci < nch; ci++) {
        const int ahead = min(2, nch - 1 - ci);
        if (ahead == 2)      asm volatile("cp.async.wait_group 2;");
        else if (ahead == 1) asm volatile("cp.async.wait_group 1;");
        else                 asm volatile("cp.async.wait_group 0;");
        __syncthreads();
        if (ci + 3 < nch) issueStage(ci + 3);

        const uint32_t base = smBase + (uint32_t)((ci & 3) * STAGE_W * 4);
        #pragma unroll
        for (int s = 0; s < 4; s++) {
            uint32_t bq[16];
            #pragma unroll
            for (int nt2 = 0; nt2 < 4; nt2++) {
                uint32_t ad = base + (uint32_t)((bRow + nt2 * 16 * FSTRIDE + s * 8) << 2);
                LDSM4(bq[nt2 * 4 + 0], bq[nt2 * 4 + 1], bq[nt2 * 4 + 2], bq[nt2 * 4 + 3], ad);
            }
            #pragma unroll
            for (int mt = 0; mt < 4; mt++) {
                uint32_t a0, a1, a2, a3;
                uint32_t ad = base + (uint32_t)((aRow + mt * 16 * FSTRIDE + s * 8) << 2);
                LDSM4(a0, a1, a2, a3, ad);
                #pragma unroll
                for (int nt = 0; nt < 8; nt++)
                    MMA_TF32(acc[mt][nt], a0, a1, a2, a3, bq[nt * 2], bq[nt * 2 + 1]);
            }
        }
    }

    // ---------------- epilogue ----------------
    float csum[8][2];
    #pragma unroll
    for (int nt = 0; nt < 8; nt++) { csum[nt][0] = 0.f; csum[nt][1] = 0.f; }

    #pragma unroll
    for (int mt = 0; mt < 4; mt++) {
        const int r0 = bm + wm * 64 + mt * 16 + g;
        #pragma unroll
        for (int nt = 0; nt < 8; nt++) {
            const int c = bn + wn * 64 + nt * 8 + tig * 2;
            float v0 = acc[mt][nt][0], v1 = acc[mt][nt][1];
            float v2 = acc[mt][nt][2], v3 = acc[mt][nt][3];
            if (bias) {
                float b0v = bias[c], b1v = bias[c + 1];
                v0 += b0v; v1 += b1v; v2 += b0v; v3 += b1v;
            }
            const size_t i0 = (size_t)r0 * ldc + c;
            const size_t i1 = (size_t)(r0 + 8) * ldc + c;
            if (mode == 1) {
                float d0, d1, d2, d3, g0, g1, g2, g3;
                gelu_both(v0, g0, d0); gelu_both(v1, g1, d1);
                gelu_both(v2, g2, d2); gelu_both(v3, g3, d3);
                *(float2*)&Caux[i0] = make_float2(d0, d1);
                *(float2*)&Caux[i1] = make_float2(d2, d3);
                v0 = g0; v1 = g1; v2 = g2; v3 = g3;
            } else if (mode == 2) {
                float2 x0 = *(const float2*)&aux[i0];
                float2 x1 = *(const float2*)&aux[i1];
                v0 *= x0.x; v1 *= x0.y; v2 *= x1.x; v3 *= x1.y;
            } else if (mode == 3) {
                v0 = gelu_f(v0); v1 = gelu_f(v1); v2 = gelu_f(v2); v3 = gelu_f(v3);
            } else if (mode == 4) {
                float2 x0 = *(const float2*)&aux[i0];
                float2 x1 = *(const float2*)&aux[i1];
                v0 += x0.x; v1 += x0.y; v2 += x1.x; v3 += x1.y;
            }
            if (roundC) {
                v0 = roundtf(v0); v1 = roundtf(v1); v2 = roundtf(v2); v3 = roundtf(v3);
            }
            *(float2*)&C[i0] = make_float2(v0, v1);
            *(float2*)&C[i1] = make_float2(v2, v3);
            if (colsum_out) { csum[nt][0] += v0 + v2; csum[nt][1] += v1 + v3; }
        }
    }

    if (colsum_out) {
        __syncthreads();
        float* cs = (float*)sm;
        if (tid < 256) cs[tid] = 0.f;
        __syncthreads();
        #pragma unroll
        for (int nt = 0; nt < 8; nt++) {
            #pragma unroll
            for (int j = 0; j < 2; j++) {
                float v = csum[nt][j];
                v += __shfl_xor_sync(0xffffffffu, v, 4);
                v += __shfl_xor_sync(0xffffffffu, v, 8);
                v += __shfl_xor_sync(0xffffffffu, v, 16);
                if (g == 0) atomicAdd(&cs[wn * 64 + nt * 8 + tig * 2 + j], v);
            }
        }
        __syncthreads();
        if (tid < 256) atomicAdd(&colsum_out[bn + tid], cs[tid]);
    }
}

// ================= slow NN GEMM (register pipeline, cvt support) =================
static constexpr int AS_STRIDE = 20;
static constexpr int A_BUFW = 128 * AS_STRIDE;
static constexpr int B_BUFW = 256 * AS_STRIDE;
static constexpr int GEMM_SMEM_BYTES = (2 * A_BUFW + 2 * B_BUFW) * 4;

__global__ void __launch_bounds__(256, 1) gemm_nn_tc(
    const float* __restrict__ A, const float* __restrict__ BT,
    const float* __restrict__ bias, float* __restrict__ C,
    int K, int lda, int ldbt, int ldc,
    int cvtA, int cvtB, int roundC)
{
    extern __shared__ uint32_t sm[];
    uint32_t* AsBuf = sm;
    uint32_t* BsBuf = sm + 2 * A_BUFW;

    const int tid = threadIdx.x, lane = tid & 31, wid = tid >> 5;
    const int wm = wid & 1, wn = wid >> 1;
    const int g = lane >> 2, tig = lane & 3;
    const int bm = blockIdx.y * 128, bn = blockIdx.x * 256;

    float acc[4][8][4] = {};

    const uint32_t smBase = (uint32_t)__cvta_generic_to_shared(sm);
    const uint32_t aAddr0 = smBase + (((wm * 64 + (lane & 15)) * AS_STRIDE + ((lane >> 4) << 2)) << 2);
    const uint32_t bAddr0 = smBase + ((2 * A_BUFW
                          + (wn * 64 + (lane & 7) + ((lane & 16) ? 8 : 0)) * AS_STRIDE
                          + ((lane & 8) ? 4 : 0)) << 2);

    float4 ra[2], rb[4];

    auto ldgAll = [&](int k0) {
        #pragma unroll
        for (int r = 0; r < 2; r++) {
            int row = (r * 256 + tid) >> 2; int kc = ((r * 256 + tid) & 3) << 2;
            ra[r] = *(const float4*)(A + (size_t)(bm + row) * lda + k0 + kc);
        }
        #pragma unroll
        for (int r = 0; r < 4; r++) {
            int row = (r * 256 + tid) >> 2; int kc = ((r * 256 + tid) & 3) << 2;
            rb[r] = *(const float4*)(BT + (size_t)(bn + row) * ldbt + k0 + kc);
        }
    };
    auto stsAll = [&](int buf) {
        #pragma unroll
        for (int r = 0; r < 2; r++) {
            int row = (r * 256 + tid) >> 2; int kc = ((r * 256 + tid) & 3) << 2;
            uint32_t* d = &AsBuf[buf * A_BUFW + row * AS_STRIDE + kc];
            if (cvtA) {
                d[0] = f2tf(ra[r].x); d[1] = f2tf(ra[r].y);
                d[2] = f2tf(ra[r].z); d[3] = f2tf(ra[r].w);
            } else { *(float4*)d = ra[r]; }
        }
        #pragma unroll
        for (int r = 0; r < 4; r++) {
            int row = (r * 256 + tid) >> 2; int kc = ((r * 256 + tid) & 3) << 2;
            uint32_t* d = &BsBuf[buf * B_BUFW + row * AS_STRIDE + kc];
            if (cvtB) {
                d[0] = f2tf(rb[r].x); d[1] = f2tf(rb[r].y);
                d[2] = f2tf(rb[r].z); d[3] = f2tf(rb[r].w);
            } else { *(float4*)d = rb[r]; }
        }
    };

    ldgAll(0);
    stsAll(0);
    if (K > 16) ldgAll(16);
    __syncthreads();

    int cur = 0;
    for (int k0 = 0; k0 < K; k0 += 16) {
        if (k0 + 16 < K) stsAll(cur ^ 1);
        if (k0 + 32 < K) ldgAll(k0 + 32);

        const uint32_t aOff = (uint32_t)(cur * A_BUFW * 4);
        const uint32_t bOff = (uint32_t)(cur * B_BUFW * 4);
        #pragma unroll
        for (int ks = 0; ks < 16; ks += 8) {
            uint32_t bq[16];
            #pragma unroll
            for (int nt2 = 0; nt2 < 4; nt2++) {
                uint32_t ad = bAddr0 + bOff + ((nt2 * 16 * AS_STRIDE + ks) << 2);
                LDSM4(bq[nt2 * 4 + 0], bq[nt2 * 4 + 1], bq[nt2 * 4 + 2], bq[nt2 * 4 + 3], ad);
            }
            #pragma unroll
            for (int mt = 0; mt < 4; mt++) {
                uint32_t a0, a1, a2, a3;
                uint32_t ad = aAddr0 + aOff + ((mt * 16 * AS_STRIDE + ks) << 2);
                LDSM4(a0, a1, a2, a3, ad);
                #pragma unroll
                for (int nt = 0; nt < 8; nt++)
                    MMA_TF32(acc[mt][nt], a0, a1, a2, a3, bq[nt * 2], bq[nt * 2 + 1]);
            }
        }
        __syncthreads();
        cur ^= 1;
    }

    #pragma unroll
    for (int mt = 0; mt < 4; mt++) {
        const int r0 = bm + wm * 64 + mt * 16 + g;
        #pragma unroll
        for (int nt = 0; nt < 8; nt++) {
            const int c = bn + wn * 64 + nt * 8 + tig * 2;
            float v0 = acc[mt][nt][0], v1 = acc[mt][nt][1];
            float v2 = acc[mt][nt][2], v3 = acc[mt][nt][3];
            if (bias) {
                float b0v = bias[c], b1v = bias[c + 1];
                v0 += b0v; v1 += b1v; v2 += b0v; v3 += b1v;
            }
            if (roundC) {
                v0 = roundtf(v0); v1 = roundtf(v1); v2 = roundtf(v2); v3 = roundtf(v3);
            }
            const size_t i0 = (size_t)r0 * ldc + c;
            const size_t i1 = (size_t)(r0 + 8) * ldc + c;
            *(float2*)&C[i0] = make_float2(v0, v1);
            *(float2*)&C[i1] = make_float2(v2, v3);
        }
    }
}

// ---------------- tensor-core TN split-K: C[M,N] += A[K,M]^T @ B[K,N] ----------------
__global__ void __launch_bounds__(256, 1) gemm_tn_tc(
    const float* __restrict__ A, const float* __restrict__ B, float* __restrict__ C,
    int K, int lda, int ldb, int ldc, int kChunk)
{
    const int tid = threadIdx.x, lane = tid & 31, wid = tid >> 5;
    const int wm = wid & 1, wn = wid >> 1;
    const int g = lane >> 2, tig = lane & 3;
    const int bm = blockIdx.y * 128, bn = blockIdx.x * 256;
    const int kb = blockIdx.z * kChunk;
    const int ke = min(K, kb + kChunk);

    float acc[4][8][4] = {};

    const float* Abase = A + bm + wm * 64 + g;
    const float* Bbase = B + bn + wn * 64 + g;

    auto loadF = [&](uint32_t (&aF)[16], uint32_t (&bF)[16], int k) {
        const float* pa = Abase + (size_t)(k + tig) * lda;
        #pragma unroll
        for (int mt = 0; mt < 4; mt++) {
            const float* p = pa + mt * 16;
            aF[mt * 4 + 0] = __float_as_uint(p[0]);
            aF[mt * 4 + 1] = __float_as_uint(p[8]);
            aF[mt * 4 + 2] = __float_as_uint(p[(size_t)4 * lda]);
            aF[mt * 4 + 3] = __float_as_uint(p[(size_t)4 * lda + 8]);
        }
        const float* pb = Bbase + (size_t)(k + tig) * ldb;
        #pragma unroll
        for (int nt = 0; nt < 8; nt++) {
            bF[nt * 2 + 0] = __float_as_uint(pb[nt * 8]);
            bF[nt * 2 + 1] = __float_as_uint(pb[(size_t)4 * ldb + nt * 8]);
        }
    };
    auto mmaAll = [&](uint32_t (&aF)[16], uint32_t (&bF)[16]) {
        #pragma unroll
        for (int mt = 0; mt < 4; mt++)
            #pragma unroll
            for (int nt = 0; nt < 8; nt++)
                MMA_TF32(acc[mt][nt], aF[mt * 4], aF[mt * 4 + 1], aF[mt * 4 + 2], aF[mt * 4 + 3],
                         bF[nt * 2], bF[nt * 2 + 1]);
    };

    uint32_t aF0[16], bF0[16], aF1[16], bF1[16];
    loadF(aF0, bF0, kb);
    for (int k = kb; k < ke; k += 16) {
        if (k + 8 < ke) loadF(aF1, bF1, k + 8);
        mmaAll(aF0, bF0);
        if (k + 16 < ke) loadF(aF0, bF0, k + 16);
        if (k + 8 < ke) mmaAll(aF1, bF1);
    }

    #pragma unroll
    for (int mt = 0; mt < 4; mt++) {
        const int r0 = bm + wm * 64 + mt * 16 + g;
        #pragma unroll
        for (int nt = 0; nt < 8; nt++) {
            const int c = bn + wn * 64 + nt * 8 + tig * 2;
            atomicAdd(&C[(size_t)r0 * ldc + c],       acc[mt][nt][0]);
            atomicAdd(&C[(size_t)r0 * ldc + c + 1],   acc[mt][nt][1]);
            atomicAdd(&C[(size_t)(r0 + 8) * ldc + c],     acc[mt][nt][2]);
            atomicAdd(&C[(size_t)(r0 + 8) * ldc + c + 1], acc[mt][nt][3]);
        }
    }
}

// ---------------- fused prep ----------------
__device__ void do_transpose32(const float* in, float* out, int R, int C, int bx, int by) {
    __shared__ float t[32][33];
    const int x = threadIdx.x & 31, y = threadIdx.x >> 5;
    const int c0 = bx * 32, r0 = by * 32;
    #pragma unroll
    for (int dy = 0; dy < 32; dy += 8)
        t[y + dy][x] = in[(size_t)(r0 + y + dy) * C + c0 + x];
    __syncthreads();
    #pragma unroll
    for (int dy = 0; dy < 32; dy += 8)
        out[(size_t)(c0 + y + dy) * R + r0 + x] = roundtf(t[x][y + dy]);
}

// block ranges:
// [0,32) WpT | [32,96) WphiT | [96,352) W1T | [352,608) W2T | [608,672) WgT
// [672,736) WpsiT | [736,800) WhT | [800,1056) WgR | [1056,2080) W2R
// [2080,2336) WphiR | [2336,2592) INR | [2592,4645) zero DW1T..DB2 (525568)
// [4645,6694) zero GT,GX,CDZ (524544) | [6694,6698) ZB2 | 6698 ZB
static constexpr int PREP_BLOCKS = 6699;

__global__ void __launch_bounds__(256) prep_all(
    const float* __restrict__ Wp, const float* __restrict__ Wphi,
    const float* __restrict__ W1, const float* __restrict__ W2,
    const float* __restrict__ Wg, const float* __restrict__ Wpsi,
    const float* __restrict__ Wh, const float* __restrict__ b2,
    const float* __restrict__ gb, const float* __restrict__ bphi,
    const float* __restrict__ b1, const float* __restrict__ inputs)
{
    float* S = g_scratch;
    const int b = blockIdx.x, tid = threadIdx.x;
    if (b < 32)        { int lb = b;        do_transpose32(Wp,   S + O_WPT,   128, CU, lb % 8,  lb / 8); }
    else if (b < 96)   { int lb = b - 32;   do_transpose32(Wphi, S + O_WPHIT, CU,  CU, lb % 8,  lb / 8); }
    else if (b < 352)  { int lb = b - 96;   do_transpose32(W1,   S + O_W1T,   CU,  CH, lb % 32, lb / 32); }
    else if (b < 608)  { int lb = b - 352;  do_transpose32(W2,   S + O_W2T,   CH,  CU, lb % 8,  lb / 8); }
    else if (b < 672)  { int lb = b - 608;  do_transpose32(Wg,   S + O_WGT,   CU,  CU, lb % 8,  lb / 8); }
    else if (b < 736)  { int lb = b - 672;  do_transpose32(Wpsi, S + O_WPSIT, CU,  CU, lb % 8,  lb / 8); }
    else if (b < 800)  { int lb = b - 736;  do_transpose32(Wh,   S + O_WHT,   CU,  CU, lb % 8,  lb / 8); }
    else if (b < 1056) { size_t i = (size_t)(b - 800)  * 256 + tid; S[O_WGR + i]   = roundtf(Wg[i]); }
    else if (b < 2080) { size_t i = (size_t)(b - 1056) * 256 + tid; S[O_W2R + i]   = roundtf(W2[i]); }
    else if (b < 2336) { size_t i = (size_t)(b - 2080) * 256 + tid; S[O_WPHIR + i] = roundtf(Wphi[i]); }
    else if (b < 2592) { size_t i = (size_t)(b - 2336) * 256 + tid; S[O_INR + i]   = roundtf(inputs[i]); }
    else if (b < 4645) { size_t i = (size_t)(b - 2592) * 256 + tid;
                         if (i < (size_t)CH*CU + (size_t)CU*CH + CH + CU) S[O_DW1T + i] = 0.f; }
    else if (b < 6694) { size_t i = (size_t)(b - 4645) * 256 + tid;
                         if (i < 2 * (size_t)CH*CU + CU) S[O_GT + i] = 0.f; }
    else if (b < 6698) {
        int n = (b - 6694) * 256 + tid;
        float s = b1[n];
        for (int k = 0; k < CU; k++) s += bphi[k] * W1[(size_t)k * CH + n];
        S[O_ZB2 + n] = s;
    } else {
        int n = tid;
        float s = gb[n];
        for (int k = 0; k < CU; k++) s += b2[k] * Wg[(size_t)k * CU + n];
        S[O_ZB + n] = s;
    }
}

// ---------------- other small kernels ----------------
__global__ void transpose_k(const float* __restrict__ in, float* __restrict__ out, int R, int C) {
    do_transpose32(in, out, R, C, blockIdx.x, blockIdx.y);
}

__global__ void roundcopy_k(const float* __restrict__ in, float* __restrict__ out, size_t n) {
    size_t i = (size_t)blockIdx.x * 256 + threadIdx.x;
    if (i < n) out[i] = roundtf(in[i]);
}

// combine: W1C = round(W1T - lr dW1T); W2C = round(W2T - lr dW2T); B1C; B2C
// grid 2053: [0,1024) W1C | [1024,2048) W2C | [2048,2052) B1C | 2052 B2C
__global__ void __launch_bounds__(256) combine_k(
    const float* __restrict__ b1, const float* __restrict__ b2)
{
    float* S = g_scratch;
    const int b = blockIdx.x, tid = threadIdx.x;
    if (b < 1024) {
        size_t i = (size_t)b * 256 + tid;
        S[O_W1C + i] = roundtf(S[O_W1T + i] - LR * S[O_DW1T + i]);
    } else if (b < 2048) {
        size_t i = (size_t)(b - 1024) * 256 + tid;
        S[O_W2C + i] = roundtf(S[O_W2T + i] - LR * S[O_DW2T + i]);
    } else if (b < 2052) {
        int n = (b - 2048) * 256 + tid;
        S[O_B1C + n] = b1[n] - LR * S[O_DB1 + n];
    } else {
        S[O_B2C + tid] = b2[tid] - LR * S[O_DB2 + tid];
    }
}

__global__ void shift_k(const float* __restrict__ seq, const float* __restrict__ proj,
                        float* __restrict__ buf_out, float* __restrict__ XR) {
    size_t idx = (size_t)blockIdx.x * 256 + threadIdx.x;
    int u = (int)(idx & (CU - 1));
    int t = (int)((idx >> 8) & (CL - 1));
    int b = (int)(idx >> 15);
    float val = (t < CL - 1) ? seq[(size_t)b * CL * CU + (size_t)(t + 1) * CU + u]
                             : proj[(size_t)b * CU + u];
    buf_out[idx] = val;
    if (t < CL - 1) XR[((size_t)b * (CL - 1) + t) * CU + u] = roundtf(val);
}

__global__ void db2_k(const float* __restrict__ Wg, const float* __restrict__ cdz,
                      float* __restrict__ db2) {
    int j = threadIdx.x;
    float s = 0.f;
    for (int k = 0; k < CU; k++) s += Wg[(size_t)j * CU + k] * cdz[k];
    db2[j] = s;
}

__global__ void colsum_k(const float* __restrict__ A, float* __restrict__ out,
                         int K, int N, int kChunk) {
    __shared__ float sh[8][33];
    const int n = blockIdx.x * 32 + (threadIdx.x & 31);
    const int kl = threadIdx.x >> 5;
    const int kb = blockIdx.y * kChunk;
    const int ke = min(K, kb + kChunk);
    float s = 0.f;
    for (int k = kb + kl; k < ke; k += 8) s += A[(size_t)k * N + n];
    sh[kl][threadIdx.x & 31] = s;
    __syncthreads();
    if (kl == 0) {
        float t = 0.f;
        #pragma unroll
        for (int i = 0; i < 8; i++) t += sh[i][threadIdx.x & 31];
        atomicAdd(&out[n], t);
    }
}

// LN fused, warp-per-row
__global__ void __launch_bounds__(256) ln_fused_k(
    const float* __restrict__ z, const float* __restrict__ buf,
    const float* __restrict__ g, const float* __restrict__ bb,
    float* __restrict__ rec, float* __restrict__ dz)
{
    const int wid = threadIdx.x >> 5, lane = threadIdx.x & 31;
    const int row = blockIdx.x * 8 + wid;
    const size_t base = (size_t)row * CU;
    const int yrow = row + (int)((unsigned)row / 127u) + 1;
    const float* zp = z + base;
    const float* yp = buf + (size_t)yrow * CU;

    float v[8], gg[8], bv[8], yv[8];
    #pragma unroll
    for (int i = 0; i < 8; i++) {
        int c = lane + i * 32;
        v[i] = zp[c]; gg[i] = g[c]; bv[i] = bb[c]; yv[i] = yp[c];
    }
    float s = v[0] + v[1] + v[2] + v[3] + v[4] + v[5] + v[6] + v[7];
    #pragma unroll
    for (int o = 16; o; o >>= 1) s += __shfl_xor_sync(0xffffffffu, s, o);
    const float m = s * (1.0f / CU);

    float d[8], s2v = 0.f;
    #pragma unroll
    for (int i = 0; i < 8; i++) { d[i] = v[i] - m; s2v += d[i] * d[i]; }
    #pragma unroll
    for (int o = 16; o; o >>= 1) s2v += __shfl_xor_sync(0xffffffffu, s2v, o);
    const float r = rsqrtf(s2v * (1.0f / CU) + 1e-3f);

    float xh[8], dxh[8], p1 = 0.f, p2 = 0.f;
    #pragma unroll
    for (int i = 0; i < 8; i++) {
        xh[i] = d[i] * r;
        float recv = gg[i] * xh[i] + bv[i];
        rec[base + lane + i * 32] = recv;
        float drec = (recv - yv[i]) * DREC_SCALE;
        dxh[i] = drec * gg[i];
        p1 += dxh[i]; p2 += dxh[i] * xh[i];
    }
    #pragma unroll
    for (int o = 16; o; o >>= 1) {
        p1 += __shfl_xor_sync(0xffffffffu, p1, o);
        p2 += __shfl_xor_sync(0xffffffffu, p2, o);
    }
    const float s1 = p1 * (1.0f / CU), sx = p2 * (1.0f / CU);
    #pragma unroll
    for (int i = 0; i < 8; i++)
        dz[base + lane + i * 32] = roundtf(r * (dxh[i] - s1 - xh[i] * sx));
}

__global__ void contrib_k(const float* __restrict__ rec, float* __restrict__ out) {
    const int b = blockIdx.x, u = threadIdx.x;
    const float* p = rec + (size_t)b * (CL - 1) * CU + u;
    float s = 0.f;
    for (int t = 0; t < CL - 1; t++) s += p[(size_t)t * CU];
    out[(size_t)b * CU + u] = s * (1.0f / (CL - 1));
}

// ---------------- launch ----------------
extern "C" void kernel_launch(void* const* d_in, const int* in_sizes, int n_in,
                              void* d_out, int out_size) {
    const float* inputs = (const float*)d_in[0];
    const float* seq  = (const float*)d_in[2];
    const float* Wp   = (const float*)d_in[3];
    const float* bp   = (const float*)d_in[4];
    const float* Wphi = (const float*)d_in[5];
    const float* bphi = (const float*)d_in[6];
    const float* Wpsi = (const float*)d_in[7];
    const float* bpsi = (const float*)d_in[8];
    const float* W1   = (const float*)d_in[9];
    const float* b1   = (const float*)d_in[10];
    const float* W2   = (const float*)d_in[11];
    const float* b2   = (const float*)d_in[12];
    const float* Wg   = (const float*)d_in[13];
    const float* gb   = (const float*)d_in[14];
    const float* lng  = (const float*)d_in[15];
    const float* lnb  = (const float*)d_in[16];
    const float* Wh   = (const float*)d_in[17];
    const float* hb   = (const float*)d_in[18];

    float* out = (float*)d_out;
    float* buf_out = out + (size_t)CB * CU;

    cudaFuncSetAttribute(gemm_nn_tc,   cudaFuncAttributeMaxDynamicSharedMemorySize, GEMM_SMEM_BYTES);
    cudaFuncSetAttribute(gemm_nn_fast, cudaFuncAttributeMaxDynamicSharedMemorySize, FAST_SMEM_BYTES);

    float* S = nullptr;
    cudaGetSymbolAddress((void**)&S, g_scratch);
    float *Z = S + O_Z, *REC = S + O_REC, *DZ = S + O_DZ, *PRE = S + O_PRE, *H = S + O_H;
    float *XR = S + O_XR;
    float *DW1T = S + O_DW1T, *DW2T = S + O_DW2T, *DB1 = S + O_DB1, *DB2 = S + O_DB2;
    float *WpT = S + O_WPT, *WphiT = S + O_WPHIT, *W1T = S + O_W1T;
    float *WpsiT = S + O_WPSIT, *WhT = S + O_WHT;
    float *WgR = S + O_WGR, *W2R = S + O_W2R, *WgT = S + O_WGT, *WphiR = S + O_WPHIR;
    float *WPW1T = S + O_WPW1T, *COMBT = S + O_COMBT, *COMB = S + O_COMB;
    float *GT = S + O_GT, *GX = S + O_GX, *CDZ = S + O_CDZ;
    float *ZB = S + O_ZB, *ZB2 = S + O_ZB2;
    float *INR = S + O_INR, *PROJ = S + O_PROJ, *PROJR = S + O_PROJR;
    float *PSI = S + O_PSI, *HPSI = S + O_HPSI, *EPSIC = S + O_EPSIC, *CONTRIB = S + O_CONTRIB;
    float *W1C = S + O_W1C, *W2C = S + O_W2C, *B1C = S + O_B1C, *B2C = S + O_B2C;

    // 0: all prep (transposes, round copies, zeros, fused biases)
    prep_all<<<PREP_BLOCKS, 256>>>(Wp, Wphi, W1, W2, Wg, Wpsi, Wh, b2, gb, bphi, b1, inputs);

    // 1: WPW1T = (Wphi@W1)^T [1024,256] = W1T @ WphiR^T; rounded
    gemm_nn_tc<<<dim3(1, CH / 128), 256, GEMM_SMEM_BYTES>>>(W1T, WphiR,
        nullptr, WPW1T, CU, CU, CU, CU, 0, 0, 1);

    // 2: proj = INR @ Wp + bp  (raw fp32 output for buf)
    gemm_nn_fast<<<dim3(1, CB / 128), 256, FAST_SMEM_BYTES>>>(INR, WpT,
        bp, PROJ, nullptr, nullptr, nullptr, 128, 128, 128, CU, 0, 0);

    // 3: shift buffer + rounded X
    shift_k<<<(CB * CL * CU) / 256, 256>>>(seq, PROJ, buf_out, XR);

    // 4: pre = XR @ (Wphi W1) + ZB2 ; H = gelu rounded, PRE = dgelu
    gemm_nn_fast<<<dim3(CH / 256, CNR / 128), 256, FAST_SMEM_BYTES>>>(XR, WPW1T,
        ZB2, H, PRE, nullptr, nullptr, CU, CU, CU, CH, 1, 1);

    // 5: PROJR = round(PROJ)
    roundcopy_k<<<(CB * CU) / 256, 256>>>(PROJ, PROJR, (size_t)CB * CU);

    // 6: COMB = W2 @ Wg [1024,256], rounded
    gemm_nn_tc<<<dim3(1, CH / 128), 256, GEMM_SMEM_BYTES>>>(W2R, WgT,
        nullptr, COMB, CU, CU, CU, CU, 0, 0, 1);

    // 7: COMBT = COMB^T (round idempotent)
    transpose_k<<<dim3(CU / 32, CH / 32), dim3(256)>>>(COMB, COMBT, CH, CU);

    // 8: z = H @ COMB + ZB
    gemm_nn_fast<<<dim3(1, CNR / 128), 256, FAST_SMEM_BYTES>>>(H, COMBT,
        ZB, Z, nullptr, nullptr, nullptr, CH, CH, CH, CU, 0, 0);

    // 9: rec = LN(z); dz rounded
    ln_fused_k<<<CNR / 8, 256>>>(Z, buf_out, lng, lnb, REC, DZ);

    // 10-11: db2 = Wg @ colsum(dz)
    colsum_k<<<dim3(CU / 32, 32), 256>>>(DZ, CDZ, CNR, CU, 2032);
    db2_k<<<1, 256>>>(Wg, CDZ, DB2);

    // 12: GT = H^T @ dz
    gemm_tn_tc<<<dim3(1, CH / 128, 32), 256>>>(H, DZ, GT, CNR, CH, CU, CU, 2032);

    // 13: dW2T = Wg @ GT^T  (GT raw -> cvtB)
    gemm_nn_tc<<<dim3(CH / 256, CU / 128), 256, GEMM_SMEM_BYTES>>>(WgR, GT,
        nullptr, DW2T, CU, CU, CU, CH, 0, 1, 0);

    // 14: dpre = (dz @ COMB^T) * dgelu + db1 colsum; rounded, in-place over PRE
    gemm_nn_fast<<<dim3(CH / 256, CNR / 128), 256, FAST_SMEM_BYTES>>>(DZ, COMB,
        nullptr, PRE, nullptr, PRE, DB1, CU, CU, CU, CH, 2, 1);

    // 15: GX = dpre^T @ XR
    gemm_tn_tc<<<dim3(1, CH / 128, 32), 256>>>(PRE, XR, GX, CNR, CH, CU, CU, 2032);

    // 16: dW1T = GX @ Wphi  (GX raw -> cvtA; BT = WphiT)
    gemm_nn_tc<<<dim3(1, CH / 128), 256, GEMM_SMEM_BYTES>>>(GX, WphiT,
        nullptr, DW1T, CU, CU, CU, CU, 1, 0, 0);

    // 17: contrib
    contrib_k<<<CB, 256>>>(REC, CONTRIB);

    // 18: psi = PROJR @ Wpsi + bpsi (rounded)
    gemm_nn_fast<<<dim3(1, CB / 128), 256, FAST_SMEM_BYTES>>>(PROJR, WpsiT,
        bpsi, PSI, nullptr, nullptr, nullptr, CU, CU, CU, CU, 0, 1);

    // 19: combined updated weights
    combine_k<<<2053, 256>>>(b1, b2);

    // 20: hpsi = gelu(PSI @ W1C + B1C) rounded
    gemm_nn_fast<<<dim3(CH / 256, CB / 128), 256, FAST_SMEM_BYTES>>>(PSI, W1C,
        B1C, HPSI, nullptr, nullptr, nullptr, CU, CU, CU, CH, 3, 1);

    // 21: epsic = round(HPSI @ W2C + B2C + contrib)
    gemm_nn_fast<<<dim3(1, CB / 128), 256, FAST_SMEM_BYTES>>>(HPSI, W2C,
        B2C, EPSIC, nullptr, CONTRIB, nullptr, CH, CH, CH, CU, 4, 1);

    // 22: out = EPSIC @ Wh + hb
    gemm_nn_fast<<<dim3(1, CB / 128), 256, FAST_SMEM_BYTES>>>(EPSIC, WhT,
        hb, out, nullptr, nullptr, nullptr, CU, CU, CU, CU, 0, 0);

    (void)in_sizes; (void)n_in; (void)out_size;
}

// round 13
// speedup vs baseline: 1.0860x; 1.0860x over previous
#include <cuda_runtime.h>
#include <math.h>
#include <stdint.h>

// ---------------- problem constants ----------------
#define CU   256
#define CL   128
#define CB   512
#define CNR  65024               // CB*(CL-1)
#define CH   1024                // 4*U

static constexpr float LR = 0.01f;
static constexpr float DREC_SCALE = 2.0f / (65024.0f * 256.0f);

// ---------------- scratch ----------------
static constexpr size_t SZ_NU = (size_t)CNR * CU;
static constexpr size_t SZ_NH = (size_t)CNR * CH;

static constexpr size_t O_PHI    = 0;
static constexpr size_t O_Z      = O_PHI + SZ_NU;
static constexpr size_t O_REC    = O_Z   + SZ_NU;
static constexpr size_t O_DZ     = O_REC + SZ_NU;
static constexpr size_t O_PRE    = O_DZ  + SZ_NU;   // holds dgelu(pre), then dpre in-place
static constexpr size_t O_H      = O_PRE + SZ_NH;
static constexpr size_t O_DW1T   = O_H   + SZ_NH;                 // [1024,256]
static constexpr size_t O_DW2T   = O_DW1T + (size_t)CH*CU;        // [256,1024]
static constexpr size_t O_DB1    = O_DW2T + (size_t)CU*CH;
static constexpr size_t O_DB2    = O_DB1 + CH;
static constexpr size_t O_WPT    = O_DB2 + CU;                    // [256,128]
static constexpr size_t O_WPHIT  = O_WPT + (size_t)CU*128;
static constexpr size_t O_W1T    = O_WPHIT + (size_t)CU*CU;       // [1024,256]
static constexpr size_t O_W2T    = O_W1T + (size_t)CH*CU;         // [256,1024]
static constexpr size_t O_WGT    = O_W2T + (size_t)CU*CH;
static constexpr size_t O_WPSIT  = O_WGT + (size_t)CU*CU;
static constexpr size_t O_WHT    = O_WPSIT + (size_t)CU*CU;
static constexpr size_t O_WGR    = O_WHT + (size_t)CU*CU;         // rounded Wg
static constexpr size_t O_W2R    = O_WGR + (size_t)CU*CU;         // rounded W2
static constexpr size_t O_COMBT  = O_W2R + (size_t)CH*CU;         // (W2@Wg)^T [256,1024]
static constexpr size_t O_COMB   = O_COMBT + (size_t)CU*CH;       // W2@Wg [1024,256]
static constexpr size_t O_GT     = O_COMB + (size_t)CH*CU;        // H^T@dz [1024,256]
static constexpr size_t O_CDZ    = O_GT + (size_t)CH*CU;          // colsum(dz) [256]
static constexpr size_t O_ZB     = O_CDZ + CU;
static constexpr size_t O_PROJ   = O_ZB + CU;
static constexpr size_t O_PSI    = O_PROJ + (size_t)CB*CU;
static constexpr size_t O_HPSI   = O_PSI  + (size_t)CB*CU;
static constexpr size_t O_EPSI   = O_HPSI + (size_t)CB*CH;
static constexpr size_t O_CONTRIB= O_EPSI + (size_t)CB*CU;
static constexpr size_t O_XR     = O_CONTRIB + (size_t)CB*CU;     // rounded X [CNR,256]
static constexpr size_t O_END    = O_XR + SZ_NU;

__device__ float g_scratch[O_END];

// ---------------- helpers ----------------
__device__ __forceinline__ float gelu_f(float x) {
    return 0.5f * x * (1.0f + erff(x * 0.7071067811865476f));
}
__device__ __forceinline__ void gelu_both(float x, float& gv, float& dv) {
    float cdf = 0.5f * (1.0f + erff(x * 0.7071067811865476f));
    gv = x * cdf;
    dv = cdf + x * 0.3989422804014327f * expf(-0.5f * x * x);
}
__device__ __forceinline__ uint32_t f2tf(float x) {
    uint32_t r; asm("cvt.rna.tf32.f32 %0, %1;" : "=r"(r) : "f"(x)); return r;
}
__device__ __forceinline__ float roundtf(float x) { return __uint_as_float(f2tf(x)); }

#define LDSM4(r0,r1,r2,r3,addr) \
    asm volatile("ldmatrix.sync.aligned.m8n8.x4.shared.b16 {%0,%1,%2,%3}, [%4];" \
                 : "=r"(r0),"=r"(r1),"=r"(r2),"=r"(r3) : "r"(addr))

#define MMA_TF32(c,a0,a1,a2,a3,b0,b1) \
    asm volatile("mma.sync.aligned.m16n8k8.row.col.f32.tf32.tf32.f32 " \
                 "{%0,%1,%2,%3},{%4,%5,%6,%7},{%8,%9},{%0,%1,%2,%3};" \
                 : "+f"(c[0]),"+f"(c[1]),"+f"(c[2]),"+f"(c[3]) \
                 : "r"(a0),"r"(a1),"r"(a2),"r"(a3),"r"(b0),"r"(b1))

#define CP16(smaddr, gptr) \
    asm volatile("cp.async.cg.shared.global [%0], [%1], 16;" :: "r"(smaddr), "l"(gptr))

// ================= FAST NN GEMM (8-warp, cp.async 3-stage, BK=32) =================
static constexpr int FSTRIDE = 36;
static constexpr int FA_STAGE = 128 * FSTRIDE;
static constexpr int FB_STAGE = 256 * FSTRIDE;
static constexpr int STAGE_W  = FA_STAGE + FB_STAGE;
static constexpr int FAST_SMEM_BYTES = 3 * STAGE_W * 4;   // 165888 B

__global__ void __launch_bounds__(256, 1) gemm_nn_fast(
    const float* __restrict__ A, const float* __restrict__ BT,
    const float* __restrict__ bias,
    float* __restrict__ C, float* __restrict__ Caux, const float* __restrict__ aux,
    float* __restrict__ colsum_out,
    int K, int lda, int ldbt, int ldc, int mode, int roundC)
{
    extern __shared__ uint32_t sm[];
    const int tid = threadIdx.x, lane = tid & 31, wid = tid >> 5;
    const int wm = wid & 1, wn = wid >> 1;
    const int g = lane >> 2, tig = lane & 3;
    const int bm = blockIdx.y * 128, bn = blockIdx.x * 256;

    float acc[4][8][4] = {};

    const uint32_t smBase = (uint32_t)__cvta_generic_to_shared(sm);
    const int aRow = (wm * 64 + (lane & 15)) * FSTRIDE + ((lane & 16) ? 4 : 0);
    const int bRow = FA_STAGE + (wn * 64 + (lane & 7) + ((lane & 16) ? 8 : 0)) * FSTRIDE
                   + ((lane & 8) ? 4 : 0);

    const int nch = K / 32;

    auto issueStage = [&](int ci) {
        const int st = ci - (ci / 3) * 3;
        uint32_t sa = smBase + (uint32_t)(st * STAGE_W * 4);
        const int k0 = ci * 32;
        #pragma unroll
        for (int t = 0; t < 4; t++) {
            int id = t * 256 + tid;
            int row = id >> 3, kc = (id & 7) << 2;
            uint32_t d = sa + (uint32_t)((row * FSTRIDE + kc) << 2);
            CP16(d, A + (size_t)(bm + row) * lda + k0 + kc);
        }
        uint32_t sb = sa + (uint32_t)(FA_STAGE * 4);
        #pragma unroll
        for (int t = 0; t < 8; t++) {
            int id = t * 256 + tid;
            int row = id >> 3, kc = (id & 7) << 2;
            uint32_t d = sb + (uint32_t)((row * FSTRIDE + kc) << 2);
            CP16(d, BT + (size_t)(bn + row) * ldbt + k0 + kc);
        }
        asm volatile("cp.async.commit_group;");
    };

    issueStage(0);
    if (nch > 1) issueStage(1);

    for (int ci = 0; ci < nch; ci++) {
        int ahead = 0;
        if (ci + 2 < nch) { issueStage(ci + 2); ahead = 2; }
        else ahead = (nch - 1) - ci;
        if (ahead == 2)      asm volatile("cp.async.wait_group 2;");
        else if (ahead == 1) asm volatile("cp.async.wait_group 1;");
        else                 asm volatile("cp.async.wait_group 0;");
        __syncthreads();

        const int st = ci - (ci / 3) * 3;
        const uint32_t base = smBase + (uint32_t)(st * STAGE_W * 4);
        #pragma unroll
        for (int s = 0; s < 4; s++) {
            uint32_t bq[16];
            #pragma unroll
            for (int nt2 = 0; nt2 < 4; nt2++) {
                uint32_t ad = base + (uint32_t)((bRow + nt2 * 16 * FSTRIDE + s * 8) << 2);
                LDSM4(bq[nt2 * 4 + 0], bq[nt2 * 4 + 1], bq[nt2 * 4 + 2], bq[nt2 * 4 + 3], ad);
            }
            #pragma unroll
            for (int mt = 0; mt < 4; mt++) {
                uint32_t a0, a1, a2, a3;
                uint32_t ad = base + (uint32_t)((aRow + mt * 16 * FSTRIDE + s * 8) << 2);
                LDSM4(a0, a1, a2, a3, ad);
                #pragma unroll
                for (int nt = 0; nt < 8; nt++)
                    MMA_TF32(acc[mt][nt], a0, a1, a2, a3, bq[nt * 2], bq[nt * 2 + 1]);
            }
        }
        __syncthreads();
    }

    // ---------------- epilogue ----------------
    float csum[8][2];
    #pragma unroll
    for (int nt = 0; nt < 8; nt++) { csum[nt][0] = 0.f; csum[nt][1] = 0.f; }

    #pragma unroll
    for (int mt = 0; mt < 4; mt++) {
        const int r0 = bm + wm * 64 + mt * 16 + g;
        #pragma unroll
        for (int nt = 0; nt < 8; nt++) {
            const int c = bn + wn * 64 + nt * 8 + tig * 2;
            float v0 = acc[mt][nt][0], v1 = acc[mt][nt][1];
            float v2 = acc[mt][nt][2], v3 = acc[mt][nt][3];
            if (bias) {
                float b0v = bias[c], b1v = bias[c + 1];
                v0 += b0v; v1 += b1v; v2 += b0v; v3 += b1v;
            }
            const size_t i0 = (size_t)r0 * ldc + c;
            const size_t i1 = (size_t)(r0 + 8) * ldc + c;
            if (mode == 1) {
                float d0, d1, d2, d3, g0, g1, g2, g3;
                gelu_both(v0, g0, d0); gelu_both(v1, g1, d1);
                gelu_both(v2, g2, d2); gelu_both(v3, g3, d3);
                *(float2*)&Caux[i0] = make_float2(d0, d1);
                *(float2*)&Caux[i1] = make_float2(d2, d3);
                v0 = g0; v1 = g1; v2 = g2; v3 = g3;
            } else if (mode == 2) {
                float2 x0 = *(const float2*)&aux[i0];
                float2 x1 = *(const float2*)&aux[i1];
                v0 *= x0.x; v1 *= x0.y; v2 *= x1.x; v3 *= x1.y;
            }
            if (roundC) {
                v0 = roundtf(v0); v1 = roundtf(v1); v2 = roundtf(v2); v3 = roundtf(v3);
            }
            *(float2*)&C[i0] = make_float2(v0, v1);
            *(float2*)&C[i1] = make_float2(v2, v3);
            if (colsum_out) { csum[nt][0] += v0 + v2; csum[nt][1] += v1 + v3; }
        }
    }

    if (colsum_out) {
        __syncthreads();
        float* cs = (float*)sm;
        if (tid < 256) cs[tid] = 0.f;
        __syncthreads();
        #pragma unroll
        for (int nt = 0; nt < 8; nt++) {
            #pragma unroll
            for (int j = 0; j < 2; j++) {
                float v = csum[nt][j];
                v += __shfl_xor_sync(0xffffffffu, v, 4);
                v += __shfl_xor_sync(0xffffffffu, v, 8);
                v += __shfl_xor_sync(0xffffffffu, v, 16);
                if (g == 0) atomicAdd(&cs[wn * 64 + nt * 8 + tig * 2 + j], v);
            }
        }
        __syncthreads();
        if (tid < 256) atomicAdd(&colsum_out[bn + tid], cs[tid]);
    }
}

// ================= slow NN GEMM (register pipeline, cvt/combine epilogues) =================
static constexpr int AS_STRIDE = 20;
static constexpr int A_BUFW = 128 * AS_STRIDE;
static constexpr int B_BUFW = 256 * AS_STRIDE;
static constexpr int GEMM_SMEM_BYTES = (2 * A_BUFW + 2 * B_BUFW) * 4;  // 61440

__global__ void __launch_bounds__(256, 1) gemm_nn_tc(
    const float* __restrict__ A, const float* __restrict__ A2,
    const float* __restrict__ BT, const float* __restrict__ B2T, float b2s,
    const float* __restrict__ bias, const float* __restrict__ bias2, float bias2s,
    float* __restrict__ C, float* __restrict__ Caux, const float* __restrict__ aux,
    int K, int lda, int ldbt, int ldc, int mode,
    int cvtA, int cvtB, int roundC)
{
    extern __shared__ uint32_t sm[];
    uint32_t* AsBuf = sm;
    uint32_t* BsBuf = sm + 2 * A_BUFW;

    const int tid = threadIdx.x, lane = tid & 31, wid = tid >> 5;
    const int wm = wid & 1, wn = wid >> 1;
    const int g = lane >> 2, tig = lane & 3;
    const int bm = blockIdx.y * 128, bn = blockIdx.x * 256;

    float acc[4][8][4] = {};

    const uint32_t smBase = (uint32_t)__cvta_generic_to_shared(sm);
    const uint32_t aAddr0 = smBase + (((wm * 64 + (lane & 15)) * AS_STRIDE + ((lane >> 4) << 2)) << 2);
    const uint32_t bAddr0 = smBase + ((2 * A_BUFW
                          + (wn * 64 + (lane & 7) + ((lane & 16) ? 8 : 0)) * AS_STRIDE
                          + ((lane & 8) ? 4 : 0)) << 2);

    float4 ra[2], rb[4];

    auto ldgAll = [&](int k0) {
        #pragma unroll
        for (int r = 0; r < 2; r++) {
            int row = (r * 256 + tid) >> 2; int kc = ((r * 256 + tid) & 3) << 2;
            float4 v = *(const float4*)(A + (size_t)(bm + row) * lda + k0 + kc);
            if (A2) {
                float4 w = *(const float4*)(A2 + (size_t)(bm + row) * lda + k0 + kc);
                v.x += w.x; v.y += w.y; v.z += w.z; v.w += w.w;
            }
            ra[r] = v;
        }
        #pragma unroll
        for (int r = 0; r < 4; r++) {
            int row = (r * 256 + tid) >> 2; int kc = ((r * 256 + tid) & 3) << 2;
            float4 v = *(const float4*)(BT + (size_t)(bn + row) * ldbt + k0 + kc);
            if (B2T) {
                float4 w = *(const float4*)(B2T + (size_t)(bn + row) * ldbt + k0 + kc);
                v.x += b2s * w.x; v.y += b2s * w.y; v.z += b2s * w.z; v.w += b2s * w.w;
            }
            rb[r] = v;
        }
    };
    auto stsAll = [&](int buf) {
        #pragma unroll
        for (int r = 0; r < 2; r++) {
            int row = (r * 256 + tid) >> 2; int kc = ((r * 256 + tid) & 3) << 2;
            uint32_t* d = &AsBuf[buf * A_BUFW + row * AS_STRIDE + kc];
            if (cvtA) {
                d[0] = f2tf(ra[r].x); d[1] = f2tf(ra[r].y);
                d[2] = f2tf(ra[r].z); d[3] = f2tf(ra[r].w);
            } else {
                *(float4*)d = ra[r];
            }
        }
        #pragma unroll
        for (int r = 0; r < 4; r++) {
            int row = (r * 256 + tid) >> 2; int kc = ((r * 256 + tid) & 3) << 2;
            uint32_t* d = &BsBuf[buf * B_BUFW + row * AS_STRIDE + kc];
            if (cvtB) {
                d[0] = f2tf(rb[r].x); d[1] = f2tf(rb[r].y);
                d[2] = f2tf(rb[r].z); d[3] = f2tf(rb[r].w);
            } else {
                *(float4*)d = rb[r];
            }
        }
    };

    ldgAll(0);
    stsAll(0);
    if (K > 16) ldgAll(16);
    __syncthreads();

    int cur = 0;
    for (int k0 = 0; k0 < K; k0 += 16) {
        if (k0 + 16 < K) stsAll(cur ^ 1);
        if (k0 + 32 < K) ldgAll(k0 + 32);

        const uint32_t aOff = (uint32_t)(cur * A_BUFW * 4);
        const uint32_t bOff = (uint32_t)(cur * B_BUFW * 4);
        #pragma unroll
        for (int ks = 0; ks < 16; ks += 8) {
            uint32_t bq[16];
            #pragma unroll
            for (int nt2 = 0; nt2 < 4; nt2++) {
                uint32_t ad = bAddr0 + bOff + ((nt2 * 16 * AS_STRIDE + ks) << 2);
                LDSM4(bq[nt2 * 4 + 0], bq[nt2 * 4 + 1], bq[nt2 * 4 + 2], bq[nt2 * 4 + 3], ad);
            }
            #pragma unroll
            for (int mt = 0; mt < 4; mt++) {
                uint32_t a0, a1, a2, a3;
                uint32_t ad = aAddr0 + aOff + ((mt * 16 * AS_STRIDE + ks) << 2);
                LDSM4(a0, a1, a2, a3, ad);
                #pragma unroll
                for (int nt = 0; nt < 8; nt++)
                    MMA_TF32(acc[mt][nt], a0, a1, a2, a3, bq[nt * 2], bq[nt * 2 + 1]);
            }
        }
        __syncthreads();
        cur ^= 1;
    }

    #pragma unroll
    for (int mt = 0; mt < 4; mt++) {
        const int r0 = bm + wm * 64 + mt * 16 + g;
        #pragma unroll
        for (int nt = 0; nt < 8; nt++) {
            const int c = bn + wn * 64 + nt * 8 + tig * 2;
            float v0 = acc[mt][nt][0], v1 = acc[mt][nt][1];
            float v2 = acc[mt][nt][2], v3 = acc[mt][nt][3];
            if (bias) {
                float b0v = bias[c], b1v = bias[c + 1];
                if (bias2) { b0v += bias2s * bias2[c]; b1v += bias2s * bias2[c + 1]; }
                v0 += b0v; v1 += b1v; v2 += b0v; v3 += b1v;
            }
            const size_t i0 = (size_t)r0 * ldc + c;
            const size_t i1 = (size_t)(r0 + 8) * ldc + c;
            if (mode == 3) {
                v0 = gelu_f(v0); v1 = gelu_f(v1); v2 = gelu_f(v2); v3 = gelu_f(v3);
            }
            if (roundC) {
                v0 = roundtf(v0); v1 = roundtf(v1); v2 = roundtf(v2); v3 = roundtf(v3);
            }
            *(float2*)&C[i0] = make_float2(v0, v1);
            *(float2*)&C[i1] = make_float2(v2, v3);
        }
    }
    (void)Caux; (void)aux; (void)mode;
}

// ---------------- tensor-core TN split-K: C[M,N] += A[K,M]^T @ B[K,N] ----------------
__global__ void __launch_bounds__(256, 1) gemm_tn_tc(
    const float* __restrict__ A, const float* __restrict__ B, float* __restrict__ C,
    int K, int lda, int ldb, int ldc, int kChunk)
{
    const int tid = threadIdx.x, lane = tid & 31, wid = tid >> 5;
    const int wm = wid & 1, wn = wid >> 1;
    const int g = lane >> 2, tig = lane & 3;
    const int bm = blockIdx.y * 128, bn = blockIdx.x * 256;
    const int kb = blockIdx.z * kChunk;
    const int ke = min(K, kb + kChunk);

    float acc[4][8][4] = {};

    const float* Abase = A + bm + wm * 64 + g;
    const float* Bbase = B + bn + wn * 64 + g;

    auto loadF = [&](uint32_t (&aF)[16], uint32_t (&bF)[16], int k) {
        const float* pa = Abase + (size_t)(k + tig) * lda;
        #pragma unroll
        for (int mt = 0; mt < 4; mt++) {
            const float* p = pa + mt * 16;
            aF[mt * 4 + 0] = __float_as_uint(p[0]);
            aF[mt * 4 + 1] = __float_as_uint(p[8]);
            aF[mt * 4 + 2] = __float_as_uint(p[(size_t)4 * lda]);
            aF[mt * 4 + 3] = __float_as_uint(p[(size_t)4 * lda + 8]);
        }
        const float* pb = Bbase + (size_t)(k + tig) * ldb;
        #pragma unroll
        for (int nt = 0; nt < 8; nt++) {
            bF[nt * 2 + 0] = __float_as_uint(pb[nt * 8]);
            bF[nt * 2 + 1] = __float_as_uint(pb[(size_t)4 * ldb + nt * 8]);
        }
    };
    auto mmaAll = [&](uint32_t (&aF)[16], uint32_t (&bF)[16]) {
        #pragma unroll
        for (int mt = 0; mt < 4; mt++)
            #pragma unroll
            for (int nt = 0; nt < 8; nt++)
                MMA_TF32(acc[mt][nt], aF[mt * 4], aF[mt * 4 + 1], aF[mt * 4 + 2], aF[mt * 4 + 3],
                         bF[nt * 2], bF[nt * 2 + 1]);
    };

    uint32_t aF0[16], bF0[16], aF1[16], bF1[16];
    loadF(aF0, bF0, kb);
    for (int k = kb; k < ke; k += 16) {
        if (k + 8 < ke) loadF(aF1, bF1, k + 8);
        mmaAll(aF0, bF0);
        if (k + 16 < ke) loadF(aF0, bF0, k + 16);
        if (k + 8 < ke) mmaAll(aF1, bF1);
    }

    #pragma unroll
    for (int mt = 0; mt < 4; mt++) {
        const int r0 = bm + wm * 64 + mt * 16 + g;
        #pragma unroll
        for (int nt = 0; nt < 8; nt++) {
            const int c = bn + wn * 64 + nt * 8 + tig * 2;
            atomicAdd(&C[(size_t)r0 * ldc + c],       acc[mt][nt][0]);
            atomicAdd(&C[(size_t)r0 * ldc + c + 1],   acc[mt][nt][1]);
            atomicAdd(&C[(size_t)(r0 + 8) * ldc + c],     acc[mt][nt][2]);
            atomicAdd(&C[(size_t)(r0 + 8) * ldc + c + 1], acc[mt][nt][3]);
        }
    }
}

// ---------------- fused prep ----------------
__device__ void do_transpose32(const float* in, float* out, int R, int C, int bx, int by) {
    __shared__ float t[32][33];
    const int x = threadIdx.x & 31, y = threadIdx.x >> 5;
    const int c0 = bx * 32, r0 = by * 32;
    #pragma unroll
    for (int dy = 0; dy < 32; dy += 8)
        t[y + dy][x] = in[(size_t)(r0 + y + dy) * C + c0 + x];
    __syncthreads();
    #pragma unroll
    for (int dy = 0; dy < 32; dy += 8)
        out[(size_t)(c0 + y + dy) * R + r0 + x] = roundtf(t[x][y + dy]);
}

static constexpr int PREP_BLOCKS = 5159;

__global__ void __launch_bounds__(256) prep_all(
    const float* __restrict__ Wp, const float* __restrict__ Wphi,
    const float* __restrict__ W1, const float* __restrict__ W2,
    const float* __restrict__ Wg, const float* __restrict__ Wpsi,
    const float* __restrict__ Wh, const float* __restrict__ b2,
    const float* __restrict__ gb)
{
    float* S = g_scratch;
    const int b = blockIdx.x, tid = threadIdx.x;
    if (b < 32)        { int lb = b;        do_transpose32(Wp,   S + O_WPT,   128, CU, lb % 8,  lb / 8); }
    else if (b < 96)   { int lb = b - 32;   do_transpose32(Wphi, S + O_WPHIT, CU,  CU, lb % 8,  lb / 8); }
    else if (b < 352)  { int lb = b - 96;   do_transpose32(W1,   S + O_W1T,   CU,  CH, lb % 32, lb / 32); }
    else if (b < 608)  { int lb = b - 352;  do_transpose32(W2,   S + O_W2T,   CH,  CU, lb % 8,  lb / 8); }
    else if (b < 672)  { int lb = b - 608;  do_transpose32(Wg,   S + O_WGT,   CU,  CU, lb % 8,  lb / 8); }
    else if (b < 736)  { int lb = b - 672;  do_transpose32(Wpsi, S + O_WPSIT, CU,  CU, lb % 8,  lb / 8); }
    else if (b < 800)  { int lb = b - 736;  do_transpose32(Wh,   S + O_WHT,   CU,  CU, lb % 8,  lb / 8); }
    else if (b < 1056) { size_t i = (size_t)(b - 800)  * 256 + tid; S[O_WGR + i] = roundtf(Wg[i]); }
    else if (b < 2080) { size_t i = (size_t)(b - 1056) * 256 + tid; S[O_W2R + i] = roundtf(W2[i]); }
    else if (b < 4133) { size_t i = (size_t)(b - 2080) * 256 + tid; S[O_DW1T + i] = 0.f; }
    else if (b < 5158) { size_t i = (size_t)(b - 4133) * 256 + tid; S[O_GT + i] = 0.f; }
    else {
        int n = tid;
        float s = gb[n];
        for (int k = 0; k < CU; k++) s += b2[k] * Wg[(size_t)k * CU + n];
        S[O_ZB + n] = s;
    }
}

// ---------------- other small kernels ----------------
__global__ void transpose_k(const float* __restrict__ in, float* __restrict__ out, int R, int C) {
    do_transpose32(in, out, R, C, blockIdx.x, blockIdx.y);
}

__global__ void shift_k(const float* __restrict__ seq, const float* __restrict__ proj,
                        float* __restrict__ buf_out, float* __restrict__ XR) {
    size_t idx = (size_t)blockIdx.x * 256 + threadIdx.x;
    int u = (int)(idx & (CU - 1));
    int t = (int)((idx >> 8) & (CL - 1));
    int b = (int)(idx >> 15);
    float val = (t < CL - 1) ? seq[(size_t)b * CL * CU + (size_t)(t + 1) * CU + u]
                             : proj[(size_t)b * CU + u];
    buf_out[idx] = val;
    if (t < CL - 1) XR[((size_t)b * (CL - 1) + t) * CU + u] = roundtf(val);
}

__global__ void db2_k(const float* __restrict__ Wg, const float* __restrict__ cdz,
                      float* __restrict__ db2) {
    int j = threadIdx.x;
    float s = 0.f;
    for (int k = 0; k < CU; k++) s += Wg[(size_t)j * CU + k] * cdz[k];
    db2[j] = s;
}

__global__ void colsum_k(const float* __restrict__ A, float* __restrict__ out,
                         int K, int N, int kChunk) {
    __shared__ float sh[8][33];
    const int n = blockIdx.x * 32 + (threadIdx.x & 31);
    const int kl = threadIdx.x >> 5;
    const int kb = blockIdx.y * kChunk;
    const int ke = min(K, kb + kChunk);
    float s = 0.f;
    for (int k = kb + kl; k < ke; k += 8) s += A[(size_t)k * N + n];
    sh[kl][threadIdx.x & 31] = s;
    __syncthreads();
    if (kl == 0) {
        float t = 0.f;
        #pragma unroll
        for (int i = 0; i < 8; i++) t += sh[i][threadIdx.x & 31];
        atomicAdd(&out[n], t);
    }
}

// ---- LN fused, warp-per-row ----
__global__ void __launch_bounds__(256) ln_fused_k(
    const float* __restrict__ z, const float* __restrict__ buf,
    const float* __restrict__ g, const float* __restrict__ bb,
    float* __restrict__ rec, float* __restrict__ dz)
{
    const int wid = threadIdx.x >> 5, lane = threadIdx.x & 31;
    const int row = blockIdx.x * 8 + wid;
    const size_t base = (size_t)row * CU;
    const int yrow = row + (int)((unsigned)row / 127u) + 1;
    const float* zp = z + base;
    const float* yp = buf + (size_t)yrow * CU;

    float v[8], gg[8], bv[8], yv[8];
    #pragma unroll
    for (int i = 0; i < 8; i++) {
        int c = lane + i * 32;
        v[i] = zp[c]; gg[i] = g[c]; bv[i] = bb[c]; yv[i] = yp[c];
    }
    float s = v[0] + v[1] + v[2] + v[3] + v[4] + v[5] + v[6] + v[7];
    #pragma unroll
    for (int o = 16; o; o >>= 1) s += __shfl_xor_sync(0xffffffffu, s, o);
    const float m = s * (1.0f / CU);

    float d[8], s2v = 0.f;
    #pragma unroll
    for (int i = 0; i < 8; i++) { d[i] = v[i] - m; s2v += d[i] * d[i]; }
    #pragma unroll
    for (int o = 16; o; o >>= 1) s2v += __shfl_xor_sync(0xffffffffu, s2v, o);
    const float r = rsqrtf(s2v * (1.0f / CU) + 1e-3f);

    float xh[8], dxh[8], p1 = 0.f, p2 = 0.f;
    #pragma unroll
    for (int i = 0; i < 8; i++) {
        xh[i] = d[i] * r;
        float recv = gg[i] * xh[i] + bv[i];
        rec[base + lane + i * 32] = recv;
        float drec = (recv - yv[i]) * DREC_SCALE;
        dxh[i] = drec * gg[i];
        p1 += dxh[i]; p2 += dxh[i] * xh[i];
    }
    #pragma unroll
    for (int o = 16; o; o >>= 1) {
        p1 += __shfl_xor_sync(0xffffffffu, p1, o);
        p2 += __shfl_xor_sync(0xffffffffu, p2, o);
    }
    const float s1 = p1 * (1.0f / CU), sx = p2 * (1.0f / CU);
    #pragma unroll
    for (int i = 0; i < 8; i++)
        dz[base + lane + i * 32] = roundtf(r * (dxh[i] - s1 - xh[i] * sx));
}

// contrib: vectorized float4, identical per-column accumulation order
__global__ void __launch_bounds__(64) contrib_k(const float* __restrict__ rec,
                                                float* __restrict__ out) {
    const int b = blockIdx.x;
    const int u4 = threadIdx.x * 4;
    const float* p = rec + (size_t)b * (CL - 1) * CU + u4;
    float4 s = make_float4(0.f, 0.f, 0.f, 0.f);
    for (int t = 0; t < CL - 1; t++) {
        float4 v = *(const float4*)(p + (size_t)t * CU);
        s.x += v.x; s.y += v.y; s.z += v.z; s.w += v.w;
    }
    const float inv = 1.0f / (CL - 1);
    s.x *= inv; s.y *= inv; s.z *= inv; s.w *= inv;
    *(float4*)&out[(size_t)b * CU + u4] = s;
}

// ---------------- launch ----------------
extern "C" void kernel_launch(void* const* d_in, const int* in_sizes, int n_in,
                              void* d_out, int out_size) {
    const float* inputs = (const float*)d_in[0];
    const float* seq  = (const float*)d_in[2];
    const float* Wp   = (const float*)d_in[3];
    const float* bp   = (const float*)d_in[4];
    const float* Wphi = (const float*)d_in[5];
    const float* bphi = (const float*)d_in[6];
    const float* Wpsi = (const float*)d_in[7];
    const float* bpsi = (const float*)d_in[8];
    const float* W1   = (const float*)d_in[9];
    const float* b1   = (const float*)d_in[10];
    const float* W2   = (const float*)d_in[11];
    const float* b2   = (const float*)d_in[12];
    const float* Wg   = (const float*)d_in[13];
    const float* gb   = (const float*)d_in[14];
    const float* lng  = (const float*)d_in[15];
    const float* lnb  = (const float*)d_in[16];
    const float* Wh   = (const float*)d_in[17];
    const float* hb   = (const float*)d_in[18];

    float* out = (float*)d_out;
    float* buf_out = out + (size_t)CB * CU;

    cudaFuncSetAttribute(gemm_nn_tc,   cudaFuncAttributeMaxDynamicSharedMemorySize, GEMM_SMEM_BYTES);
    cudaFuncSetAttribute(gemm_nn_fast, cudaFuncAttributeMaxDynamicSharedMemorySize, FAST_SMEM_BYTES);

    float* S = nullptr;
    cudaGetSymbolAddress((void**)&S, g_scratch);
    float *PHI = S + O_PHI, *Z = S + O_Z, *REC = S + O_REC, *DZ = S + O_DZ;
    float *PRE = S + O_PRE, *H = S + O_H;
    float *DW1T = S + O_DW1T, *DW2T = S + O_DW2T, *DB1 = S + O_DB1, *DB2 = S + O_DB2;
    float *WpT = S + O_WPT, *WphiT = S + O_WPHIT, *W1T = S + O_W1T, *W2T = S + O_W2T;
    float *WpsiT = S + O_WPSIT, *WhT = S + O_WHT;
    float *WgR = S + O_WGR, *W2R = S + O_W2R, *WgT = S + O_WGT;
    float *COMBT = S + O_COMBT, *COMB = S + O_COMB, *GT = S + O_GT, *CDZ = S + O_CDZ;
    float *ZB = S + O_ZB;
    float *PROJ = S + O_PROJ, *PSI = S + O_PSI;
    float *HPSI = S + O_HPSI, *EPSI = S + O_EPSI, *CONTRIB = S + O_CONTRIB;
    float *XR = S + O_XR;

    // 0: all prep
    prep_all<<<PREP_BLOCKS, 256>>>(Wp, Wphi, W1, W2, Wg, Wpsi, Wh, b2, gb);

    // 1: proj = inputs @ Wp + bp
    gemm_nn_tc<<<dim3(1, CB / 128), 256, GEMM_SMEM_BYTES>>>(inputs, nullptr, WpT, nullptr, 0.f,
        bp, nullptr, 0.f, PROJ, nullptr, nullptr, 128, 128, 128, CU, 0, 1, 0, 0);

    // 2: shift buffer + rounded X
    shift_k<<<(CB * CL * CU) / 256, 256>>>(seq, PROJ, buf_out, XR);

    // 3 (ncu-profiled): phi = XR @ Wphi + bphi (rounded output)
    gemm_nn_fast<<<dim3(1, CNR / 128), 256, FAST_SMEM_BYTES>>>(XR, WphiT,
        bphi, PHI, nullptr, nullptr, nullptr, CU, CU, CU, CU, 0, 1);

    // 4: COMB = W2 @ Wg [1024,256], rounded
    gemm_nn_tc<<<dim3(1, CH / 128), 256, GEMM_SMEM_BYTES>>>(W2R, nullptr, WgT, nullptr, 0.f,
        nullptr, nullptr, 0.f, COMB, nullptr, nullptr, CU, CU, CU, CU, 0, 0, 0, 1);

    // 5: COMBT = COMB^T
    transpose_k<<<dim3(CU / 32, CH / 32), dim3(256)>>>(COMB, COMBT, CH, CU);

    // pre = phi@W1+b1 ; H = gelu(pre) rounded, PRE := dgelu(pre)
    gemm_nn_fast<<<dim3(CH / 256, CNR / 128), 256, FAST_SMEM_BYTES>>>(PHI, W1T,
        b1, H, PRE, nullptr, nullptr, CU, CU, CU, CH, 1, 1);

    // z = H @ (W2@Wg) + (b2@Wg + gb)
    gemm_nn_fast<<<dim3(1, CNR / 128), 256, FAST_SMEM_BYTES>>>(H, COMBT,
        ZB, Z, nullptr, nullptr, nullptr, CH, CH, CH, CU, 0, 0);

    // rec = LN(z); dz = LN_bwd(...) rounded
    ln_fused_k<<<CNR / 8, 256>>>(Z, buf_out, lng, lnb, REC, DZ);

    // cdz = colsum(dz); db2 = Wg @ cdz
    colsum_k<<<dim3(CU / 32, 32), 256>>>(DZ, CDZ, CNR, CU, 2032);
    db2_k<<<1, 256>>>(Wg, CDZ, DB2);

    // GT = H^T @ dz  [1024,256]  (64 splits)
    gemm_tn_tc<<<dim3(1, CH / 128, 64), 256>>>(H, DZ, GT, CNR, CH, CU, CU, 1016);

    // dW2T = Wg @ GT^T  [256,1024]
    gemm_nn_tc<<<dim3(CH / 256, CU / 128), 256, GEMM_SMEM_BYTES>>>(WgR, nullptr, GT, nullptr, 0.f,
        nullptr, nullptr, 0.f, DW2T, nullptr, nullptr, CU, CU, CU, CH, 0, 0, 1, 0);

    // dpre = (dz @ COMB^T) * stored-dgelu + db1 colsum; rounded, in-place over PRE
    gemm_nn_fast<<<dim3(CH / 256, CNR / 128), 256, FAST_SMEM_BYTES>>>(DZ, COMB,
        nullptr, PRE, nullptr, PRE, DB1, CU, CU, CU, CH, 2, 1);

    // dW1T = dpre^T @ phi  (64 splits)
    gemm_tn_tc<<<dim3(1, CH / 128, 64), 256>>>(PRE, PHI, DW1T, CNR, CH, CU, CU, 1016);

    contrib_k<<<CB, 64>>>(REC, CONTRIB);

    // psi = proj @ Wpsi + bpsi  (rounded output)
    gemm_nn_tc<<<dim3(1, CB / 128), 256, GEMM_SMEM_BYTES>>>(PROJ, nullptr, WpsiT, nullptr, 0.f,
        bpsi, nullptr, 0.f, PSI, nullptr, nullptr, CU, CU, CU, CU, 0, 1, 0, 1);

    // hpsi = gelu(psi @ (W1 - lr dW1) + (b1 - lr db1))
    gemm_nn_tc<<<dim3(CH / 256, CB / 128), 256, GEMM_SMEM_BYTES>>>(PSI, nullptr, W1T, DW1T, -LR,
        b1, DB1, -LR, HPSI, nullptr, nullptr, CU, CU, CU, CH, 3, 0, 1, 1);

    // epsi = hpsi @ (W2 - lr dW2) + (b2 - lr db2)
    gemm_nn_tc<<<dim3(1, CB / 128), 256, GEMM_SMEM_BYTES>>>(HPSI, nullptr, W2T, DW2T, -LR,
        b2, DB2, -LR, EPSI, nullptr, nullptr, CH, CH, CH, CU, 0, 0, 1, 0);

    // out = (epsi + contrib) @ Wh + h_bias
    gemm_nn_tc<<<dim3(1, CB / 128), 256, GEMM_SMEM_BYTES>>>(EPSI, CONTRIB, WhT, nullptr, 0.f,
        hb, nullptr, 0.f, out, nullptr, nullptr, CU, CU, CU, CU, 0, 1, 0, 0);

    (void)in_sizes; (void)n_in; (void)out_size;
}

// round 14
// speedup vs baseline: 1.1459x; 1.0552x over previous
#include <cuda_runtime.h>
#include <math.h>
#include <stdint.h>

// ---------------- problem constants ----------------
#define CU   256
#define CL   128
#define CB   512
#define CNR  65024               // CB*(CL-1)
#define CH   1024                // 4*U

static constexpr float LR = 0.01f;
static constexpr float DREC_SCALE = 2.0f / (65024.0f * 256.0f);

// ---------------- scratch ----------------
static constexpr size_t SZ_NU = (size_t)CNR * CU;
static constexpr size_t SZ_NH = (size_t)CNR * CH;

static constexpr size_t O_PHI    = 0;
static constexpr size_t O_Z      = O_PHI + SZ_NU;
static constexpr size_t O_REC    = O_Z   + SZ_NU;
static constexpr size_t O_DZ     = O_REC + SZ_NU;
static constexpr size_t O_PRE    = O_DZ  + SZ_NU;   // holds dgelu(pre), then dpre in-place
static constexpr size_t O_H      = O_PRE + SZ_NH;
static constexpr size_t O_DW1T   = O_H   + SZ_NH;                 // [1024,256]
static constexpr size_t O_DW2T   = O_DW1T + (size_t)CH*CU;        // [256,1024]
static constexpr size_t O_DB1    = O_DW2T + (size_t)CU*CH;
static constexpr size_t O_DB2    = O_DB1 + CH;
static constexpr size_t O_WPT    = O_DB2 + CU;                    // [256,128]
static constexpr size_t O_WPHIT  = O_WPT + (size_t)CU*128;
static constexpr size_t O_W1T    = O_WPHIT + (size_t)CU*CU;       // [1024,256]
static constexpr size_t O_W2T    = O_W1T + (size_t)CH*CU;         // [256,1024]
static constexpr size_t O_WGT    = O_W2T + (size_t)CU*CH;
static constexpr size_t O_WPSIT  = O_WGT + (size_t)CU*CU;
static constexpr size_t O_WHT    = O_WPSIT + (size_t)CU*CU;
static constexpr size_t O_WGR    = O_WHT + (size_t)CU*CU;         // rounded Wg
static constexpr size_t O_W2R    = O_WGR + (size_t)CU*CU;         // rounded W2
static constexpr size_t O_COMBT  = O_W2R + (size_t)CH*CU;         // (W2@Wg)^T [256,1024]
static constexpr size_t O_COMB   = O_COMBT + (size_t)CU*CH;       // W2@Wg [1024,256]
static constexpr size_t O_GT     = O_COMB + (size_t)CH*CU;        // H^T@dz [1024,256]
static constexpr size_t O_CDZ    = O_GT + (size_t)CH*CU;          // colsum(dz) [256]
static constexpr size_t O_ZB     = O_CDZ + CU;
static constexpr size_t O_PROJ   = O_ZB + CU;
static constexpr size_t O_PSI    = O_PROJ + (size_t)CB*CU;
static constexpr size_t O_HPSI   = O_PSI  + (size_t)CB*CU;
static constexpr size_t O_EPSI   = O_HPSI + (size_t)CB*CH;
static constexpr size_t O_CONTRIB= O_EPSI + (size_t)CB*CU;
static constexpr size_t O_XR     = O_CONTRIB + (size_t)CB*CU;     // rounded X [CNR,256]
static constexpr size_t O_END    = O_XR + SZ_NU;

__device__ float g_scratch[O_END];

// ---------------- helpers ----------------
__device__ __forceinline__ float gelu_f(float x) {
    return 0.5f * x * (1.0f + erff(x * 0.7071067811865476f));
}
__device__ __forceinline__ void gelu_both(float x, float& gv, float& dv) {
    float cdf = 0.5f * (1.0f + erff(x * 0.7071067811865476f));
    gv = x * cdf;
    dv = cdf + x * 0.3989422804014327f * expf(-0.5f * x * x);
}
__device__ __forceinline__ uint32_t f2tf(float x) {
    uint32_t r; asm("cvt.rna.tf32.f32 %0, %1;" : "=r"(r) : "f"(x)); return r;
}
__device__ __forceinline__ float roundtf(float x) { return __uint_as_float(f2tf(x)); }

#define LDSM4(r0,r1,r2,r3,addr) \
    asm volatile("ldmatrix.sync.aligned.m8n8.x4.shared.b16 {%0,%1,%2,%3}, [%4];" \
                 : "=r"(r0),"=r"(r1),"=r"(r2),"=r"(r3) : "r"(addr))

#define MMA_TF32(c,a0,a1,a2,a3,b0,b1) \
    asm volatile("mma.sync.aligned.m16n8k8.row.col.f32.tf32.tf32.f32 " \
                 "{%0,%1,%2,%3},{%4,%5,%6,%7},{%8,%9},{%0,%1,%2,%3};" \
                 : "+f"(c[0]),"+f"(c[1]),"+f"(c[2]),"+f"(c[3]) \
                 : "r"(a0),"r"(a1),"r"(a2),"r"(a3),"r"(b0),"r"(b1))

#define CP16(smaddr, gptr) \
    asm volatile("cp.async.cg.shared.global [%0], [%1], 16;" :: "r"(smaddr), "l"(gptr))

// ===== FAST NN GEMM: 128 threads, 4 warps (2x2), tile 128x128, 3-stage, 2 CTAs/SM =====
static constexpr int FSTRIDE = 36;
static constexpr int FA_STAGE = 128 * FSTRIDE;
static constexpr int FB_STAGE = 128 * FSTRIDE;
static constexpr int STAGE_W  = FA_STAGE + FB_STAGE;      // 9216 words
static constexpr int FAST_SMEM_BYTES = 3 * STAGE_W * 4;   // 110592 B -> 2 CTAs/SM

__global__ void __launch_bounds__(128, 2) gemm_nn_fast(
    const float* __restrict__ A, const float* __restrict__ BT,
    const float* __restrict__ bias,
    float* __restrict__ C, float* __restrict__ Caux, const float* __restrict__ aux,
    float* __restrict__ colsum_out,
    int K, int lda, int ldbt, int ldc, int mode, int roundC)
{
    extern __shared__ uint32_t sm[];
    const int tid = threadIdx.x, lane = tid & 31, wid = tid >> 5;
    const int wm = wid & 1, wn = (wid >> 1) & 1;
    const int g = lane >> 2, tig = lane & 3;
    const int bm = blockIdx.y * 128, bn = blockIdx.x * 128;

    float acc[4][8][4] = {};

    const uint32_t smBase = (uint32_t)__cvta_generic_to_shared(sm);
    const int aRow = (wm * 64 + (lane & 15)) * FSTRIDE + ((lane & 16) ? 4 : 0);
    const int bRow = FA_STAGE + (wn * 64 + (lane & 7) + ((lane & 16) ? 8 : 0)) * FSTRIDE
                   + ((lane & 8) ? 4 : 0);

    const int nch = K / 32;

    auto issueStage = [&](int ci) {
        const int st = ci - (ci / 3) * 3;
        uint32_t sa = smBase + (uint32_t)(st * STAGE_W * 4);
        const int k0 = ci * 32;
        #pragma unroll
        for (int t = 0; t < 8; t++) {                 // A: 128 rows x 8 chunks / 128 thr
            int id = t * 128 + tid;
            int row = id >> 3, kc = (id & 7) << 2;
            uint32_t d = sa + (uint32_t)((row * FSTRIDE + kc) << 2);
            CP16(d, A + (size_t)(bm + row) * lda + k0 + kc);
        }
        uint32_t sb = sa + (uint32_t)(FA_STAGE * 4);
        #pragma unroll
        for (int t = 0; t < 8; t++) {                 // B: 128 rows x 8 chunks
            int id = t * 128 + tid;
            int row = id >> 3, kc = (id & 7) << 2;
            uint32_t d = sb + (uint32_t)((row * FSTRIDE + kc) << 2);
            CP16(d, BT + (size_t)(bn + row) * ldbt + k0 + kc);
        }
        asm volatile("cp.async.commit_group;");
    };

    issueStage(0);
    if (nch > 1) issueStage(1);

    for (int ci = 0; ci < nch; ci++) {
        int ahead = 0;
        if (ci + 2 < nch) { issueStage(ci + 2); ahead = 2; }
        else ahead = (nch - 1) - ci;
        if (ahead == 2)      asm volatile("cp.async.wait_group 2;");
        else if (ahead == 1) asm volatile("cp.async.wait_group 1;");
        else                 asm volatile("cp.async.wait_group 0;");
        __syncthreads();

        const int st = ci - (ci / 3) * 3;
        const uint32_t base = smBase + (uint32_t)(st * STAGE_W * 4);
        #pragma unroll
        for (int s = 0; s < 4; s++) {
            uint32_t bq[16];
            #pragma unroll
            for (int nt2 = 0; nt2 < 4; nt2++) {
                uint32_t ad = base + (uint32_t)((bRow + nt2 * 16 * FSTRIDE + s * 8) << 2);
                LDSM4(bq[nt2 * 4 + 0], bq[nt2 * 4 + 1], bq[nt2 * 4 + 2], bq[nt2 * 4 + 3], ad);
            }
            #pragma unroll
            for (int mt = 0; mt < 4; mt++) {
                uint32_t a0, a1, a2, a3;
                uint32_t ad = base + (uint32_t)((aRow + mt * 16 * FSTRIDE + s * 8) << 2);
                LDSM4(a0, a1, a2, a3, ad);
                #pragma unroll
                for (int nt = 0; nt < 8; nt++)
                    MMA_TF32(acc[mt][nt], a0, a1, a2, a3, bq[nt * 2], bq[nt * 2 + 1]);
            }
        }
        __syncthreads();
    }

    // ---------------- epilogue ----------------
    float csum[8][2];
    #pragma unroll
    for (int nt = 0; nt < 8; nt++) { csum[nt][0] = 0.f; csum[nt][1] = 0.f; }

    #pragma unroll
    for (int mt = 0; mt < 4; mt++) {
        const int r0 = bm + wm * 64 + mt * 16 + g;
        #pragma unroll
        for (int nt = 0; nt < 8; nt++) {
            const int c = bn + wn * 64 + nt * 8 + tig * 2;
            float v0 = acc[mt][nt][0], v1 = acc[mt][nt][1];
            float v2 = acc[mt][nt][2], v3 = acc[mt][nt][3];
            if (bias) {
                float b0v = bias[c], b1v = bias[c + 1];
                v0 += b0v; v1 += b1v; v2 += b0v; v3 += b1v;
            }
            const size_t i0 = (size_t)r0 * ldc + c;
            const size_t i1 = (size_t)(r0 + 8) * ldc + c;
            if (mode == 1) {
                float d0, d1, d2, d3, g0, g1, g2, g3;
                gelu_both(v0, g0, d0); gelu_both(v1, g1, d1);
                gelu_both(v2, g2, d2); gelu_both(v3, g3, d3);
                *(float2*)&Caux[i0] = make_float2(d0, d1);
                *(float2*)&Caux[i1] = make_float2(d2, d3);
                v0 = g0; v1 = g1; v2 = g2; v3 = g3;
            } else if (mode == 2) {
                float2 x0 = *(const float2*)&aux[i0];
                float2 x1 = *(const float2*)&aux[i1];
                v0 *= x0.x; v1 *= x0.y; v2 *= x1.x; v3 *= x1.y;
            }
            if (roundC) {
                v0 = roundtf(v0); v1 = roundtf(v1); v2 = roundtf(v2); v3 = roundtf(v3);
            }
            *(float2*)&C[i0] = make_float2(v0, v1);
            *(float2*)&C[i1] = make_float2(v2, v3);
            if (colsum_out) { csum[nt][0] += v0 + v2; csum[nt][1] += v1 + v3; }
        }
    }

    if (colsum_out) {
        __syncthreads();
        float* cs = (float*)sm;
        cs[tid] = 0.f;                                 // 128 entries
        __syncthreads();
        #pragma unroll
        for (int nt = 0; nt < 8; nt++) {
            #pragma unroll
            for (int j = 0; j < 2; j++) {
                float v = csum[nt][j];
                v += __shfl_xor_sync(0xffffffffu, v, 4);
                v += __shfl_xor_sync(0xffffffffu, v, 8);
                v += __shfl_xor_sync(0xffffffffu, v, 16);
                if (g == 0) atomicAdd(&cs[wn * 64 + nt * 8 + tig * 2 + j], v);
            }
        }
        __syncthreads();
        atomicAdd(&colsum_out[bn + tid], cs[tid]);
    }
}

// ================= slow NN GEMM (register pipeline, cvt/combine epilogues) =================
static constexpr int AS_STRIDE = 20;
static constexpr int A_BUFW = 128 * AS_STRIDE;
static constexpr int B_BUFW = 256 * AS_STRIDE;
static constexpr int GEMM_SMEM_BYTES = (2 * A_BUFW + 2 * B_BUFW) * 4;  // 61440

__global__ void __launch_bounds__(256, 1) gemm_nn_tc(
    const float* __restrict__ A, const float* __restrict__ A2,
    const float* __restrict__ BT, const float* __restrict__ B2T, float b2s,
    const float* __restrict__ bias, const float* __restrict__ bias2, float bias2s,
    float* __restrict__ C, float* __restrict__ Caux, const float* __restrict__ aux,
    int K, int lda, int ldbt, int ldc, int mode,
    int cvtA, int cvtB, int roundC)
{
    extern __shared__ uint32_t sm[];
    uint32_t* AsBuf = sm;
    uint32_t* BsBuf = sm + 2 * A_BUFW;

    const int tid = threadIdx.x, lane = tid & 31, wid = tid >> 5;
    const int wm = wid & 1, wn = wid >> 1;
    const int g = lane >> 2, tig = lane & 3;
    const int bm = blockIdx.y * 128, bn = blockIdx.x * 256;

    float acc[4][8][4] = {};

    const uint32_t smBase = (uint32_t)__cvta_generic_to_shared(sm);
    const uint32_t aAddr0 = smBase + (((wm * 64 + (lane & 15)) * AS_STRIDE + ((lane >> 4) << 2)) << 2);
    const uint32_t bAddr0 = smBase + ((2 * A_BUFW
                          + (wn * 64 + (lane & 7) + ((lane & 16) ? 8 : 0)) * AS_STRIDE
                          + ((lane & 8) ? 4 : 0)) << 2);

    float4 ra[2], rb[4];

    auto ldgAll = [&](int k0) {
        #pragma unroll
        for (int r = 0; r < 2; r++) {
            int row = (r * 256 + tid) >> 2; int kc = ((r * 256 + tid) & 3) << 2;
            float4 v = *(const float4*)(A + (size_t)(bm + row) * lda + k0 + kc);
            if (A2) {
                float4 w = *(const float4*)(A2 + (size_t)(bm + row) * lda + k0 + kc);
                v.x += w.x; v.y += w.y; v.z += w.z; v.w += w.w;
            }
            ra[r] = v;
        }
        #pragma unroll
        for (int r = 0; r < 4; r++) {
            int row = (r * 256 + tid) >> 2; int kc = ((r * 256 + tid) & 3) << 2;
            float4 v = *(const float4*)(BT + (size_t)(bn + row) * ldbt + k0 + kc);
            if (B2T) {
                float4 w = *(const float4*)(B2T + (size_t)(bn + row) * ldbt + k0 + kc);
                v.x += b2s * w.x; v.y += b2s * w.y; v.z += b2s * w.z; v.w += b2s * w.w;
            }
            rb[r] = v;
        }
    };
    auto stsAll = [&](int buf) {
        #pragma unroll
        for (int r = 0; r < 2; r++) {
            int row = (r * 256 + tid) >> 2; int kc = ((r * 256 + tid) & 3) << 2;
            uint32_t* d = &AsBuf[buf * A_BUFW + row * AS_STRIDE + kc];
            if (cvtA) {
                d[0] = f2tf(ra[r].x); d[1] = f2tf(ra[r].y);
                d[2] = f2tf(ra[r].z); d[3] = f2tf(ra[r].w);
            } else {
                *(float4*)d = ra[r];
            }
        }
        #pragma unroll
        for (int r = 0; r < 4; r++) {
            int row = (r * 256 + tid) >> 2; int kc = ((r * 256 + tid) & 3) << 2;
            uint32_t* d = &BsBuf[buf * B_BUFW + row * AS_STRIDE + kc];
            if (cvtB) {
                d[0] = f2tf(rb[r].x); d[1] = f2tf(rb[r].y);
                d[2] = f2tf(rb[r].z); d[3] = f2tf(rb[r].w);
            } else {
                *(float4*)d = rb[r];
            }
        }
    };

    ldgAll(0);
    stsAll(0);
    if (K > 16) ldgAll(16);
    __syncthreads();

    int cur = 0;
    for (int k0 = 0; k0 < K; k0 += 16) {
        if (k0 + 16 < K) stsAll(cur ^ 1);
        if (k0 + 32 < K) ldgAll(k0 + 32);

        const uint32_t aOff = (uint32_t)(cur * A_BUFW * 4);
        const uint32_t bOff = (uint32_t)(cur * B_BUFW * 4);
        #pragma unroll
        for (int ks = 0; ks < 16; ks += 8) {
            uint32_t bq[16];
            #pragma unroll
            for (int nt2 = 0; nt2 < 4; nt2++) {
                uint32_t ad = bAddr0 + bOff + ((nt2 * 16 * AS_STRIDE + ks) << 2);
                LDSM4(bq[nt2 * 4 + 0], bq[nt2 * 4 + 1], bq[nt2 * 4 + 2], bq[nt2 * 4 + 3], ad);
            }
            #pragma unroll
            for (int mt = 0; mt < 4; mt++) {
                uint32_t a0, a1, a2, a3;
                uint32_t ad = aAddr0 + aOff + ((mt * 16 * AS_STRIDE + ks) << 2);
                LDSM4(a0, a1, a2, a3, ad);
                #pragma unroll
                for (int nt = 0; nt < 8; nt++)
                    MMA_TF32(acc[mt][nt], a0, a1, a2, a3, bq[nt * 2], bq[nt * 2 + 1]);
            }
        }
        __syncthreads();
        cur ^= 1;
    }

    #pragma unroll
    for (int mt = 0; mt < 4; mt++) {
        const int r0 = bm + wm * 64 + mt * 16 + g;
        #pragma unroll
        for (int nt = 0; nt < 8; nt++) {
            const int c = bn + wn * 64 + nt * 8 + tig * 2;
            float v0 = acc[mt][nt][0], v1 = acc[mt][nt][1];
            float v2 = acc[mt][nt][2], v3 = acc[mt][nt][3];
            if (bias) {
                float b0v = bias[c], b1v = bias[c + 1];
                if (bias2) { b0v += bias2s * bias2[c]; b1v += bias2s * bias2[c + 1]; }
                v0 += b0v; v1 += b1v; v2 += b0v; v3 += b1v;
            }
            const size_t i0 = (size_t)r0 * ldc + c;
            const size_t i1 = (size_t)(r0 + 8) * ldc + c;
            if (mode == 3) {
                v0 = gelu_f(v0); v1 = gelu_f(v1); v2 = gelu_f(v2); v3 = gelu_f(v3);
            }
            if (roundC) {
                v0 = roundtf(v0); v1 = roundtf(v1); v2 = roundtf(v2); v3 = roundtf(v3);
            }
            *(float2*)&C[i0] = make_float2(v0, v1);
            *(float2*)&C[i1] = make_float2(v2, v3);
        }
    }
    (void)Caux; (void)aux; (void)mode;
}

// ---------------- tensor-core TN split-K: C[M,N] += A[K,M]^T @ B[K,N] ----------------
__global__ void __launch_bounds__(256, 1) gemm_tn_tc(
    const float* __restrict__ A, const float* __restrict__ B, float* __restrict__ C,
    int K, int lda, int ldb, int ldc, int kChunk)
{
    const int tid = threadIdx.x, lane = tid & 31, wid = tid >> 5;
    const int wm = wid & 1, wn = wid >> 1;
    const int g = lane >> 2, tig = lane & 3;
    const int bm = blockIdx.y * 128, bn = blockIdx.x * 256;
    const int kb = blockIdx.z * kChunk;
    const int ke = min(K, kb + kChunk);

    float acc[4][8][4] = {};

    const float* Abase = A + bm + wm * 64 + g;
    const float* Bbase = B + bn + wn * 64 + g;

    auto loadF = [&](uint32_t (&aF)[16], uint32_t (&bF)[16], int k) {
        const float* pa = Abase + (size_t)(k + tig) * lda;
        #pragma unroll
        for (int mt = 0; mt < 4; mt++) {
            const float* p = pa + mt * 16;
            aF[mt * 4 + 0] = __float_as_uint(p[0]);
            aF[mt * 4 + 1] = __float_as_uint(p[8]);
            aF[mt * 4 + 2] = __float_as_uint(p[(size_t)4 * lda]);
            aF[mt * 4 + 3] = __float_as_uint(p[(size_t)4 * lda + 8]);
        }
        const float* pb = Bbase + (size_t)(k + tig) * ldb;
        #pragma unroll
        for (int nt = 0; nt < 8; nt++) {
            bF[nt * 2 + 0] = __float_as_uint(pb[nt * 8]);
            bF[nt * 2 + 1] = __float_as_uint(pb[(size_t)4 * ldb + nt * 8]);
        }
    };
    auto mmaAll = [&](uint32_t (&aF)[16], uint32_t (&bF)[16]) {
        #pragma unroll
        for (int mt = 0; mt < 4; mt++)
            #pragma unroll
            for (int nt = 0; nt < 8; nt++)
                MMA_TF32(acc[mt][nt], aF[mt * 4], aF[mt * 4 + 1], aF[mt * 4 + 2], aF[mt * 4 + 3],
                         bF[nt * 2], bF[nt * 2 + 1]);
    };

    uint32_t aF0[16], bF0[16], aF1[16], bF1[16];
    loadF(aF0, bF0, kb);
    for (int k = kb; k < ke; k += 16) {
        if (k + 8 < ke) loadF(aF1, bF1, k + 8);
        mmaAll(aF0, bF0);
        if (k + 16 < ke) loadF(aF0, bF0, k + 16);
        if (k + 8 < ke) mmaAll(aF1, bF1);
    }

    #pragma unroll
    for (int mt = 0; mt < 4; mt++) {
        const int r0 = bm + wm * 64 + mt * 16 + g;
        #pragma unroll
        for (int nt = 0; nt < 8; nt++) {
            const int c = bn + wn * 64 + nt * 8 + tig * 2;
            atomicAdd(&C[(size_t)r0 * ldc + c],       acc[mt][nt][0]);
            atomicAdd(&C[(size_t)r0 * ldc + c + 1],   acc[mt][nt][1]);
            atomicAdd(&C[(size_t)(r0 + 8) * ldc + c],     acc[mt][nt][2]);
            atomicAdd(&C[(size_t)(r0 + 8) * ldc + c + 1], acc[mt][nt][3]);
        }
    }
}

// ---------------- fused prep ----------------
__device__ void do_transpose32(const float* in, float* out, int R, int C, int bx, int by) {
    __shared__ float t[32][33];
    const int x = threadIdx.x & 31, y = threadIdx.x >> 5;
    const int c0 = bx * 32, r0 = by * 32;
    #pragma unroll
    for (int dy = 0; dy < 32; dy += 8)
        t[y + dy][x] = in[(size_t)(r0 + y + dy) * C + c0 + x];
    __syncthreads();
    #pragma unroll
    for (int dy = 0; dy < 32; dy += 8)
        out[(size_t)(c0 + y + dy) * R + r0 + x] = roundtf(t[x][y + dy]);
}

static constexpr int PREP_BLOCKS = 5159;

__global__ void __launch_bounds__(256) prep_all(
    const float* __restrict__ Wp, const float* __restrict__ Wphi,
    const float* __restrict__ W1, const float* __restrict__ W2,
    const float* __restrict__ Wg, const float* __restrict__ Wpsi,
    const float* __restrict__ Wh, const float* __restrict__ b2,
    const float* __restrict__ gb)
{
    float* S = g_scratch;
    const int b = blockIdx.x, tid = threadIdx.x;
    if (b < 32)        { int lb = b;        do_transpose32(Wp,   S + O_WPT,   128, CU, lb % 8,  lb / 8); }
    else if (b < 96)   { int lb = b - 32;   do_transpose32(Wphi, S + O_WPHIT, CU,  CU, lb % 8,  lb / 8); }
    else if (b < 352)  { int lb = b - 96;   do_transpose32(W1,   S + O_W1T,   CU,  CH, lb % 32, lb / 32); }
    else if (b < 608)  { int lb = b - 352;  do_transpose32(W2,   S + O_W2T,   CH,  CU, lb % 8,  lb / 8); }
    else if (b < 672)  { int lb = b - 608;  do_transpose32(Wg,   S + O_WGT,   CU,  CU, lb % 8,  lb / 8); }
    else if (b < 736)  { int lb = b - 672;  do_transpose32(Wpsi, S + O_WPSIT, CU,  CU, lb % 8,  lb / 8); }
    else if (b < 800)  { int lb = b - 736;  do_transpose32(Wh,   S + O_WHT,   CU,  CU, lb % 8,  lb / 8); }
    else if (b < 1056) { size_t i = (size_t)(b - 800)  * 256 + tid; S[O_WGR + i] = roundtf(Wg[i]); }
    else if (b < 2080) { size_t i = (size_t)(b - 1056) * 256 + tid; S[O_W2R + i] = roundtf(W2[i]); }
    else if (b < 4133) { size_t i = (size_t)(b - 2080) * 256 + tid; S[O_DW1T + i] = 0.f; }
    else if (b < 5158) { size_t i = (size_t)(b - 4133) * 256 + tid; S[O_GT + i] = 0.f; }
    else {
        int n = tid;
        float s = gb[n];
        for (int k = 0; k < CU; k++) s += b2[k] * Wg[(size_t)k * CU + n];
        S[O_ZB + n] = s;
    }
}

// ---------------- other small kernels ----------------
__global__ void transpose_k(const float* __restrict__ in, float* __restrict__ out, int R, int C) {
    do_transpose32(in, out, R, C, blockIdx.x, blockIdx.y);
}

__global__ void shift_k(const float* __restrict__ seq, const float* __restrict__ proj,
                        float* __restrict__ buf_out, float* __restrict__ XR) {
    size_t idx = (size_t)blockIdx.x * 256 + threadIdx.x;
    int u = (int)(idx & (CU - 1));
    int t = (int)((idx >> 8) & (CL - 1));
    int b = (int)(idx >> 15);
    float val = (t < CL - 1) ? seq[(size_t)b * CL * CU + (size_t)(t + 1) * CU + u]
                             : proj[(size_t)b * CU + u];
    buf_out[idx] = val;
    if (t < CL - 1) XR[((size_t)b * (CL - 1) + t) * CU + u] = roundtf(val);
}

__global__ void db2_k(const float* __restrict__ Wg, const float* __restrict__ cdz,
                      float* __restrict__ db2) {
    int j = threadIdx.x;
    float s = 0.f;
    for (int k = 0; k < CU; k++) s += Wg[(size_t)j * CU + k] * cdz[k];
    db2[j] = s;
}

__global__ void colsum_k(const float* __restrict__ A, float* __restrict__ out,
                         int K, int N, int kChunk) {
    __shared__ float sh[8][33];
    const int n = blockIdx.x * 32 + (threadIdx.x & 31);
    const int kl = threadIdx.x >> 5;
    const int kb = blockIdx.y * kChunk;
    const int ke = min(K, kb + kChunk);
    float s = 0.f;
    for (int k = kb + kl; k < ke; k += 8) s += A[(size_t)k * N + n];
    sh[kl][threadIdx.x & 31] = s;
    __syncthreads();
    if (kl == 0) {
        float t = 0.f;
        #pragma unroll
        for (int i = 0; i < 8; i++) t += sh[i][threadIdx.x & 31];
        atomicAdd(&out[n], t);
    }
}

// ---- LN fused, warp-per-row ----
__global__ void __launch_bounds__(256) ln_fused_k(
    const float* __restrict__ z, const float* __restrict__ buf,
    const float* __restrict__ g, const float* __restrict__ bb,
    float* __restrict__ rec, float* __restrict__ dz)
{
    const int wid = threadIdx.x >> 5, lane = threadIdx.x & 31;
    const int row = blockIdx.x * 8 + wid;
    const size_t base = (size_t)row * CU;
    const int yrow = row + (int)((unsigned)row / 127u) + 1;
    const float* zp = z + base;
    const float* yp = buf + (size_t)yrow * CU;

    float v[8], gg[8], bv[8], yv[8];
    #pragma unroll
    for (int i = 0; i < 8; i++) {
        int c = lane + i * 32;
        v[i] = zp[c]; gg[i] = g[c]; bv[i] = bb[c]; yv[i] = yp[c];
    }
    float s = v[0] + v[1] + v[2] + v[3] + v[4] + v[5] + v[6] + v[7];
    #pragma unroll
    for (int o = 16; o; o >>= 1) s += __shfl_xor_sync(0xffffffffu, s, o);
    const float m = s * (1.0f / CU);

    float d[8], s2v = 0.f;
    #pragma unroll
    for (int i = 0; i < 8; i++) { d[i] = v[i] - m; s2v += d[i] * d[i]; }
    #pragma unroll
    for (int o = 16; o; o >>= 1) s2v += __shfl_xor_sync(0xffffffffu, s2v, o);
    const float r = rsqrtf(s2v * (1.0f / CU) + 1e-3f);

    float xh[8], dxh[8], p1 = 0.f, p2 = 0.f;
    #pragma unroll
    for (int i = 0; i < 8; i++) {
        xh[i] = d[i] * r;
        float recv = gg[i] * xh[i] + bv[i];
        rec[base + lane + i * 32] = recv;
        float drec = (recv - yv[i]) * DREC_SCALE;
        dxh[i] = drec * gg[i];
        p1 += dxh[i]; p2 += dxh[i] * xh[i];
    }
    #pragma unroll
    for (int o = 16; o; o >>= 1) {
        p1 += __shfl_xor_sync(0xffffffffu, p1, o);
        p2 += __shfl_xor_sync(0xffffffffu, p2, o);
    }
    const float s1 = p1 * (1.0f / CU), sx = p2 * (1.0f / CU);
    #pragma unroll
    for (int i = 0; i < 8; i++)
        dz[base + lane + i * 32] = roundtf(r * (dxh[i] - s1 - xh[i] * sx));
}

__global__ void contrib_k(const float* __restrict__ rec, float* __restrict__ out) {
    const int b = blockIdx.x, u = threadIdx.x;
    const float* p = rec + (size_t)b * (CL - 1) * CU + u;
    float s = 0.f;
    for (int t = 0; t < CL - 1; t++) s += p[(size_t)t * CU];
    out[(size_t)b * CU + u] = s * (1.0f / (CL - 1));
}

// ---------------- launch ----------------
extern "C" void kernel_launch(void* const* d_in, const int* in_sizes, int n_in,
                              void* d_out, int out_size) {
    const float* inputs = (const float*)d_in[0];
    const float* seq  = (const float*)d_in[2];
    const float* Wp   = (const float*)d_in[3];
    const float* bp   = (const float*)d_in[4];
    const float* Wphi = (const float*)d_in[5];
    const float* bphi = (const float*)d_in[6];
    const float* Wpsi = (const float*)d_in[7];
    const float* bpsi = (const float*)d_in[8];
    const float* W1   = (const float*)d_in[9];
    const float* b1   = (const float*)d_in[10];
    const float* W2   = (const float*)d_in[11];
    const float* b2   = (const float*)d_in[12];
    const float* Wg   = (const float*)d_in[13];
    const float* gb   = (const float*)d_in[14];
    const float* lng  = (const float*)d_in[15];
    const float* lnb  = (const float*)d_in[16];
    const float* Wh   = (const float*)d_in[17];
    const float* hb   = (const float*)d_in[18];

    float* out = (float*)d_out;
    float* buf_out = out + (size_t)CB * CU;

    cudaFuncSetAttribute(gemm_nn_tc,   cudaFuncAttributeMaxDynamicSharedMemorySize, GEMM_SMEM_BYTES);
    cudaFuncSetAttribute(gemm_nn_fast, cudaFuncAttributeMaxDynamicSharedMemorySize, FAST_SMEM_BYTES);

    float* S = nullptr;
    cudaGetSymbolAddress((void**)&S, g_scratch);
    float *PHI = S + O_PHI, *Z = S + O_Z, *REC = S + O_REC, *DZ = S + O_DZ;
    float *PRE = S + O_PRE, *H = S + O_H;
    float *DW1T = S + O_DW1T, *DW2T = S + O_DW2T, *DB1 = S + O_DB1, *DB2 = S + O_DB2;
    float *WpT = S + O_WPT, *WphiT = S + O_WPHIT, *W1T = S + O_W1T, *W2T = S + O_W2T;
    float *WpsiT = S + O_WPSIT, *WhT = S + O_WHT;
    float *WgR = S + O_WGR, *W2R = S + O_W2R, *WgT = S + O_WGT;
    float *COMBT = S + O_COMBT, *COMB = S + O_COMB, *GT = S + O_GT, *CDZ = S + O_CDZ;
    float *ZB = S + O_ZB;
    float *PROJ = S + O_PROJ, *PSI = S + O_PSI;
    float *HPSI = S + O_HPSI, *EPSI = S + O_EPSI, *CONTRIB = S + O_CONTRIB;
    float *XR = S + O_XR;

    // 0: all prep
    prep_all<<<PREP_BLOCKS, 256>>>(Wp, Wphi, W1, W2, Wg, Wpsi, Wh, b2, gb);

    // 1: proj = inputs @ Wp + bp
    gemm_nn_tc<<<dim3(1, CB / 128), 256, GEMM_SMEM_BYTES>>>(inputs, nullptr, WpT, nullptr, 0.f,
        bp, nullptr, 0.f, PROJ, nullptr, nullptr, 128, 128, 128, CU, 0, 1, 0, 0);

    // 2: shift buffer + rounded X
    shift_k<<<(CB * CL * CU) / 256, 256>>>(seq, PROJ, buf_out, XR);

    // 3 (ncu-profiled): phi = XR @ Wphi + bphi (rounded output)
    gemm_nn_fast<<<dim3(CU / 128, CNR / 128), 128, FAST_SMEM_BYTES>>>(XR, WphiT,
        bphi, PHI, nullptr, nullptr, nullptr, CU, CU, CU, CU, 0, 1);

    // 4: COMB = W2 @ Wg [1024,256], rounded
    gemm_nn_tc<<<dim3(1, CH / 128), 256, GEMM_SMEM_BYTES>>>(W2R, nullptr, WgT, nullptr, 0.f,
        nullptr, nullptr, 0.f, COMB, nullptr, nullptr, CU, CU, CU, CU, 0, 0, 0, 1);

    // 5: COMBT = COMB^T
    transpose_k<<<dim3(CU / 32, CH / 32), dim3(256)>>>(COMB, COMBT, CH, CU);

    // pre = phi@W1+b1 ; H = gelu(pre) rounded, PRE := dgelu(pre)
    gemm_nn_fast<<<dim3(CH / 128, CNR / 128), 128, FAST_SMEM_BYTES>>>(PHI, W1T,
        b1, H, PRE, nullptr, nullptr, CU, CU, CU, CH, 1, 1);

    // z = H @ (W2@Wg) + (b2@Wg + gb)
    gemm_nn_fast<<<dim3(CU / 128, CNR / 128), 128, FAST_SMEM_BYTES>>>(H, COMBT,
        ZB, Z, nullptr, nullptr, nullptr, CH, CH, CH, CU, 0, 0);

    // rec = LN(z); dz = LN_bwd(...) rounded
    ln_fused_k<<<CNR / 8, 256>>>(Z, buf_out, lng, lnb, REC, DZ);

    // cdz = colsum(dz); db2 = Wg @ cdz
    colsum_k<<<dim3(CU / 32, 32), 256>>>(DZ, CDZ, CNR, CU, 2032);
    db2_k<<<1, 256>>>(Wg, CDZ, DB2);

    // GT = H^T @ dz  [1024,256]  (32 splits — R10 setting)
    gemm_tn_tc<<<dim3(1, CH / 128, 32), 256>>>(H, DZ, GT, CNR, CH, CU, CU, 2032);

    // dW2T = Wg @ GT^T  [256,1024]
    gemm_nn_tc<<<dim3(CH / 256, CU / 128), 256, GEMM_SMEM_BYTES>>>(WgR, nullptr, GT, nullptr, 0.f,
        nullptr, nullptr, 0.f, DW2T, nullptr, nullptr, CU, CU, CU, CH, 0, 0, 1, 0);

    // dpre = (dz @ COMB^T) * stored-dgelu + db1 colsum; rounded, in-place over PRE
    gemm_nn_fast<<<dim3(CH / 128, CNR / 128), 128, FAST_SMEM_BYTES>>>(DZ, COMB,
        nullptr, PRE, nullptr, PRE, DB1, CU, CU, CU, CH, 2, 1);

    // dW1T = dpre^T @ phi  (32 splits)
    gemm_tn_tc<<<dim3(1, CH / 128, 32), 256>>>(PRE, PHI, DW1T, CNR, CH, CU, CU, 2032);

    contrib_k<<<CB, 256>>>(REC, CONTRIB);

    // psi = proj @ Wpsi + bpsi  (rounded output)
    gemm_nn_tc<<<dim3(1, CB / 128), 256, GEMM_SMEM_BYTES>>>(PROJ, nullptr, WpsiT, nullptr, 0.f,
        bpsi, nullptr, 0.f, PSI, nullptr, nullptr, CU, CU, CU, CU, 0, 1, 0, 1);

    // hpsi = gelu(psi @ (W1 - lr dW1) + (b1 - lr db1))
    gemm_nn_tc<<<dim3(CH / 256, CB / 128), 256, GEMM_SMEM_BYTES>>>(PSI, nullptr, W1T, DW1T, -LR,
        b1, DB1, -LR, HPSI, nullptr, nullptr, CU, CU, CU, CH, 3, 0, 1, 1);

    // epsi = hpsi @ (W2 - lr dW2) + (b2 - lr db2)
    gemm_nn_tc<<<dim3(1, CB / 128), 256, GEMM_SMEM_BYTES>>>(HPSI, nullptr, W2T, DW2T, -LR,
        b2, DB2, -LR, EPSI, nullptr, nullptr, CH, CH, CH, CU, 0, 0, 1, 0);

    // out = (epsi + contrib) @ Wh + h_bias
    gemm_nn_tc<<<dim3(1, CB / 128), 256, GEMM_SMEM_BYTES>>>(EPSI, CONTRIB, WhT, nullptr, 0.f,
        hb, nullptr, 0.f, out, nullptr, nullptr, CU, CU, CU, CU, 0, 1, 0, 0);

    (void)in_sizes; (void)n_in; (void)out_size;
}

// round 15
// speedup vs baseline: 1.3024x; 1.1365x over previous
#include <cuda_runtime.h>
#include <math.h>
#include <stdint.h>

// ---------------- problem constants ----------------
#define CU   256
#define CL   128
#define CB   512
#define CNR  65024               // CB*(CL-1)
#define CH   1024                // 4*U

static constexpr float LR = 0.01f;
static constexpr float DREC_SCALE = 2.0f / (65024.0f * 256.0f);

// ---------------- scratch ----------------
static constexpr size_t SZ_NU = (size_t)CNR * CU;
static constexpr size_t SZ_NH = (size_t)CNR * CH;

static constexpr size_t O_PHI    = 0;
static constexpr size_t O_Z      = O_PHI + SZ_NU;
static constexpr size_t O_REC    = O_Z   + SZ_NU;
static constexpr size_t O_DZ     = O_REC + SZ_NU;
static constexpr size_t O_PRE    = O_DZ  + SZ_NU;   // holds dgelu(pre), then dpre in-place
static constexpr size_t O_H      = O_PRE + SZ_NH;
static constexpr size_t O_DW1T   = O_H   + SZ_NH;                 // [1024,256]
static constexpr size_t O_DW2T   = O_DW1T + (size_t)CH*CU;        // [256,1024]
static constexpr size_t O_DB1    = O_DW2T + (size_t)CU*CH;
static constexpr size_t O_DB2    = O_DB1 + CH;
static constexpr size_t O_WPT    = O_DB2 + CU;                    // [256,128]
static constexpr size_t O_WPHIT  = O_WPT + (size_t)CU*128;
static constexpr size_t O_W1T    = O_WPHIT + (size_t)CU*CU;       // [1024,256]
static constexpr size_t O_W2T    = O_W1T + (size_t)CH*CU;         // [256,1024]
static constexpr size_t O_WGT    = O_W2T + (size_t)CU*CH;
static constexpr size_t O_WPSIT  = O_WGT + (size_t)CU*CU;
static constexpr size_t O_WHT    = O_WPSIT + (size_t)CU*CU;
static constexpr size_t O_WGR    = O_WHT + (size_t)CU*CU;         // rounded Wg
static constexpr size_t O_W2R    = O_WGR + (size_t)CU*CU;         // rounded W2
static constexpr size_t O_COMBT  = O_W2R + (size_t)CH*CU;         // (W2@Wg)^T [256,1024]
static constexpr size_t O_COMB   = O_COMBT + (size_t)CU*CH;       // W2@Wg [1024,256]
static constexpr size_t O_GT     = O_COMB + (size_t)CH*CU;        // H^T@dz [1024,256]
static constexpr size_t O_CDZ    = O_GT + (size_t)CH*CU;          // colsum(dz) [256]
static constexpr size_t O_ZB     = O_CDZ + CU;
static constexpr size_t O_PROJ   = O_ZB + CU;
static constexpr size_t O_PSI    = O_PROJ + (size_t)CB*CU;
static constexpr size_t O_HPSI   = O_PSI  + (size_t)CB*CU;
static constexpr size_t O_EPSI   = O_HPSI + (size_t)CB*CH;
static constexpr size_t O_CONTRIB= O_EPSI + (size_t)CB*CU;
static constexpr size_t O_XR     = O_CONTRIB + (size_t)CB*CU;     // rounded X [CNR,256]
static constexpr size_t O_END    = O_XR + SZ_NU;

__device__ float g_scratch[O_END];

// ---------------- helpers ----------------
__device__ __forceinline__ float gelu_f(float x) {
    return 0.5f * x * (1.0f + erff(x * 0.7071067811865476f));
}
__device__ __forceinline__ void gelu_both(float x, float& gv, float& dv) {
    float cdf = 0.5f * (1.0f + erff(x * 0.7071067811865476f));
    gv = x * cdf;
    dv = cdf + x * 0.3989422804014327f * expf(-0.5f * x * x);
}
__device__ __forceinline__ uint32_t f2tf(float x) {
    uint32_t r; asm("cvt.rna.tf32.f32 %0, %1;" : "=r"(r) : "f"(x)); return r;
}
__device__ __forceinline__ float roundtf(float x) { return __uint_as_float(f2tf(x)); }

#define LDSM4(r0,r1,r2,r3,addr) \
    asm volatile("ldmatrix.sync.aligned.m8n8.x4.shared.b16 {%0,%1,%2,%3}, [%4];" \
                 : "=r"(r0),"=r"(r1),"=r"(r2),"=r"(r3) : "r"(addr))

#define MMA_TF32(c,a0,a1,a2,a3,b0,b1) \
    asm volatile("mma.sync.aligned.m16n8k8.row.col.f32.tf32.tf32.f32 " \
                 "{%0,%1,%2,%3},{%4,%5,%6,%7},{%8,%9},{%0,%1,%2,%3};" \
                 : "+f"(c[0]),"+f"(c[1]),"+f"(c[2]),"+f"(c[3]) \
                 : "r"(a0),"r"(a1),"r"(a2),"r"(a3),"r"(b0),"r"(b1))

#define MMA_TF32F(c,a0,a1,a2,a3,b0,b1) \
    asm volatile("mma.sync.aligned.m16n8k8.row.col.f32.tf32.tf32.f32 " \
                 "{%0,%1,%2,%3},{%4,%5,%6,%7},{%8,%9},{%0,%1,%2,%3};" \
                 : "+f"(c[0]),"+f"(c[1]),"+f"(c[2]),"+f"(c[3]) \
                 : "r"(__float_as_uint(a0)),"r"(__float_as_uint(a1)), \
                   "r"(__float_as_uint(a2)),"r"(__float_as_uint(a3)), \
                   "r"(__float_as_uint(b0)),"r"(__float_as_uint(b1)))

#define CP16(smaddr, gptr) \
    asm volatile("cp.async.cg.shared.global [%0], [%1], 16;" :: "r"(smaddr), "l"(gptr))

// ===== FAST NN GEMM: 128 threads, 4 warps (2x2), tile 128x128, 3-stage, 2 CTAs/SM =====
static constexpr int FSTRIDE = 36;
static constexpr int FA_STAGE = 128 * FSTRIDE;
static constexpr int FB_STAGE = 128 * FSTRIDE;
static constexpr int STAGE_W  = FA_STAGE + FB_STAGE;      // 9216 words
static constexpr int FAST_SMEM_BYTES = 3 * STAGE_W * 4;   // 110592 B -> 2 CTAs/SM

__global__ void __launch_bounds__(128, 2) gemm_nn_fast(
    const float* __restrict__ A, const float* __restrict__ BT,
    const float* __restrict__ bias,
    float* __restrict__ C, float* __restrict__ Caux, const float* __restrict__ aux,
    float* __restrict__ colsum_out,
    int K, int lda, int ldbt, int ldc, int mode, int roundC)
{
    extern __shared__ uint32_t sm[];
    const int tid = threadIdx.x, lane = tid & 31, wid = tid >> 5;
    const int wm = wid & 1, wn = (wid >> 1) & 1;
    const int g = lane >> 2, tig = lane & 3;
    const int bm = blockIdx.y * 128, bn = blockIdx.x * 128;

    float acc[4][8][4] = {};

    const uint32_t smBase = (uint32_t)__cvta_generic_to_shared(sm);
    const int aRow = (wm * 64 + (lane & 15)) * FSTRIDE + ((lane & 16) ? 4 : 0);
    const int bRow = FA_STAGE + (wn * 64 + (lane & 7) + ((lane & 16) ? 8 : 0)) * FSTRIDE
                   + ((lane & 8) ? 4 : 0);

    const int nch = K / 32;

    auto issueStage = [&](int ci) {
        const int st = ci - (ci / 3) * 3;
        uint32_t sa = smBase + (uint32_t)(st * STAGE_W * 4);
        const int k0 = ci * 32;
        #pragma unroll
        for (int t = 0; t < 8; t++) {
            int id = t * 128 + tid;
            int row = id >> 3, kc = (id & 7) << 2;
            uint32_t d = sa + (uint32_t)((row * FSTRIDE + kc) << 2);
            CP16(d, A + (size_t)(bm + row) * lda + k0 + kc);
        }
        uint32_t sb = sa + (uint32_t)(FA_STAGE * 4);
        #pragma unroll
        for (int t = 0; t < 8; t++) {
            int id = t * 128 + tid;
            int row = id >> 3, kc = (id & 7) << 2;
            uint32_t d = sb + (uint32_t)((row * FSTRIDE + kc) << 2);
            CP16(d, BT + (size_t)(bn + row) * ldbt + k0 + kc);
        }
        asm volatile("cp.async.commit_group;");
    };

    issueStage(0);
    if (nch > 1) issueStage(1);

    for (int ci = 0; ci < nch; ci++) {
        int ahead = 0;
        if (ci + 2 < nch) { issueStage(ci + 2); ahead = 2; }
        else ahead = (nch - 1) - ci;
        if (ahead == 2)      asm volatile("cp.async.wait_group 2;");
        else if (ahead == 1) asm volatile("cp.async.wait_group 1;");
        else                 asm volatile("cp.async.wait_group 0;");
        __syncthreads();

        const int st = ci - (ci / 3) * 3;
        const uint32_t base = smBase + (uint32_t)(st * STAGE_W * 4);
        #pragma unroll
        for (int s = 0; s < 4; s++) {
            uint32_t bq[16];
            #pragma unroll
            for (int nt2 = 0; nt2 < 4; nt2++) {
                uint32_t ad = base + (uint32_t)((bRow + nt2 * 16 * FSTRIDE + s * 8) << 2);
                LDSM4(bq[nt2 * 4 + 0], bq[nt2 * 4 + 1], bq[nt2 * 4 + 2], bq[nt2 * 4 + 3], ad);
            }
            #pragma unroll
            for (int mt = 0; mt < 4; mt++) {
                uint32_t a0, a1, a2, a3;
                uint32_t ad = base + (uint32_t)((aRow + mt * 16 * FSTRIDE + s * 8) << 2);
                LDSM4(a0, a1, a2, a3, ad);
                #pragma unroll
                for (int nt = 0; nt < 8; nt++)
                    MMA_TF32(acc[mt][nt], a0, a1, a2, a3, bq[nt * 2], bq[nt * 2 + 1]);
            }
        }
        __syncthreads();
    }

    // ---------------- epilogue ----------------
    float csum[8][2];
    #pragma unroll
    for (int nt = 0; nt < 8; nt++) { csum[nt][0] = 0.f; csum[nt][1] = 0.f; }

    #pragma unroll
    for (int mt = 0; mt < 4; mt++) {
        const int r0 = bm + wm * 64 + mt * 16 + g;
        #pragma unroll
        for (int nt = 0; nt < 8; nt++) {
            const int c = bn + wn * 64 + nt * 8 + tig * 2;
            float v0 = acc[mt][nt][0], v1 = acc[mt][nt][1];
            float v2 = acc[mt][nt][2], v3 = acc[mt][nt][3];
            if (bias) {
                float b0v = bias[c], b1v = bias[c + 1];
                v0 += b0v; v1 += b1v; v2 += b0v; v3 += b1v;
            }
            const size_t i0 = (size_t)r0 * ldc + c;
            const size_t i1 = (size_t)(r0 + 8) * ldc + c;
            if (mode == 1) {
                float d0, d1, d2, d3, g0, g1, g2, g3;
                gelu_both(v0, g0, d0); gelu_both(v1, g1, d1);
                gelu_both(v2, g2, d2); gelu_both(v3, g3, d3);
                *(float2*)&Caux[i0] = make_float2(d0, d1);
                *(float2*)&Caux[i1] = make_float2(d2, d3);
                v0 = g0; v1 = g1; v2 = g2; v3 = g3;
            } else if (mode == 2) {
                float2 x0 = *(const float2*)&aux[i0];
                float2 x1 = *(const float2*)&aux[i1];
                v0 *= x0.x; v1 *= x0.y; v2 *= x1.x; v3 *= x1.y;
            }
            if (roundC) {
                v0 = roundtf(v0); v1 = roundtf(v1); v2 = roundtf(v2); v3 = roundtf(v3);
            }
            *(float2*)&C[i0] = make_float2(v0, v1);
            *(float2*)&C[i1] = make_float2(v2, v3);
            if (colsum_out) { csum[nt][0] += v0 + v2; csum[nt][1] += v1 + v3; }
        }
    }

    if (colsum_out) {
        __syncthreads();
        float* cs = (float*)sm;
        cs[tid] = 0.f;
        __syncthreads();
        #pragma unroll
        for (int nt = 0; nt < 8; nt++) {
            #pragma unroll
            for (int j = 0; j < 2; j++) {
                float v = csum[nt][j];
                v += __shfl_xor_sync(0xffffffffu, v, 4);
                v += __shfl_xor_sync(0xffffffffu, v, 8);
                v += __shfl_xor_sync(0xffffffffu, v, 16);
                if (g == 0) atomicAdd(&cs[wn * 64 + nt * 8 + tig * 2 + j], v);
            }
        }
        __syncthreads();
        atomicAdd(&colsum_out[bn + tid], cs[tid]);
    }
}

// ===== FAST TN split-K: C[M,N] += A[K,M]^T @ B[K,N] — staged smem, direct-LDS frags =====
// 128 threads, 4 warps (2x2), tile 128x128, K-chunk 32, cp.async 3-stage, 2 CTAs/SM.
static constexpr int TSTRIDE  = 132;                      // floats per k-row (128 + 4 pad)
static constexpr int TA_STAGE = 32 * TSTRIDE;             // 4224 words
static constexpr int TSTAGE_W = 2 * TA_STAGE;             // 8448 words
static constexpr int TN_SMEM_BYTES = 3 * TSTAGE_W * 4;    // 101376 B -> 2 CTAs/SM

__global__ void __launch_bounds__(128, 2) gemm_tn_fast(
    const float* __restrict__ A, const float* __restrict__ B, float* __restrict__ C,
    int K, int lda, int ldb, int ldc, int kChunk)
{
    extern __shared__ float smf[];
    const int tid = threadIdx.x, lane = tid & 31, wid = tid >> 5;
    const int wm = wid & 1, wn = (wid >> 1) & 1;
    const int g = lane >> 2, tig = lane & 3;
    const int bm = blockIdx.y * 128, bn = blockIdx.x * 128;
    const int kb = blockIdx.z * kChunk;
    const int ke = min(K, kb + kChunk);
    const int nch = (ke - kb) >> 5;

    float acc[4][8][4] = {};

    const uint32_t smBase = (uint32_t)__cvta_generic_to_shared(smf);

    auto issueStage = [&](int ci) {
        const int st = ci - (ci / 3) * 3;
        const int k0 = kb + ci * 32;
        uint32_t sa = smBase + (uint32_t)(st * TSTAGE_W * 4);
        #pragma unroll
        for (int t = 0; t < 8; t++) {              // A: 32 k-rows x 128 m
            int id = t * 128 + tid;
            int kk = id >> 5, mg = id & 31;
            uint32_t d = sa + (uint32_t)((kk * TSTRIDE + mg * 4) << 2);
            CP16(d, A + (size_t)(k0 + kk) * lda + bm + mg * 4);
        }
        uint32_t sb = sa + (uint32_t)(TA_STAGE * 4);
        #pragma unroll
        for (int t = 0; t < 8; t++) {              // B: 32 k-rows x 128 n
            int id = t * 128 + tid;
            int kk = id >> 5, mg = id & 31;
            uint32_t d = sb + (uint32_t)((kk * TSTRIDE + mg * 4) << 2);
            CP16(d, B + (size_t)(k0 + kk) * ldb + bn + mg * 4);
        }
        asm volatile("cp.async.commit_group;");
    };

    issueStage(0);
    if (nch > 1) issueStage(1);

    for (int ci = 0; ci < nch; ci++) {
        int ahead = 0;
        if (ci + 2 < nch) { issueStage(ci + 2); ahead = 2; }
        else ahead = (nch - 1) - ci;
        if (ahead == 2)      asm volatile("cp.async.wait_group 2;");
        else if (ahead == 1) asm volatile("cp.async.wait_group 1;");
        else                 asm volatile("cp.async.wait_group 0;");
        __syncthreads();

        const int st = ci - (ci / 3) * 3;
        const float* As = smf + st * TSTAGE_W;
        const float* Bs = As + TA_STAGE;
        #pragma unroll
        for (int s = 0; s < 4; s++) {
            const int kr0 = s * 8 + tig;           // rows tig and tig+4 of this 8-k step
            const float* a_lo = As + kr0 * TSTRIDE;
            const float* a_hi = As + (kr0 + 4) * TSTRIDE;
            const float* b_lo = Bs + kr0 * TSTRIDE;
            const float* b_hi = Bs + (kr0 + 4) * TSTRIDE;

            float bq[8][2];
            #pragma unroll
            for (int nt = 0; nt < 8; nt++) {
                const int nb = wn * 64 + nt * 8 + g;
                bq[nt][0] = b_lo[nb];
                bq[nt][1] = b_hi[nb];
            }
            #pragma unroll
            for (int mt = 0; mt < 4; mt++) {
                const int mb = wm * 64 + mt * 16 + g;
                float a0 = a_lo[mb], a1 = a_lo[mb + 8];
                float a2 = a_hi[mb], a3 = a_hi[mb + 8];
                #pragma unroll
                for (int nt = 0; nt < 8; nt++)
                    MMA_TF32F(acc[mt][nt], a0, a1, a2, a3, bq[nt][0], bq[nt][1]);
            }
        }
        __syncthreads();
    }

    #pragma unroll
    for (int mt = 0; mt < 4; mt++) {
        const int r0 = bm + wm * 64 + mt * 16 + g;
        #pragma unroll
        for (int nt = 0; nt < 8; nt++) {
            const int c = bn + wn * 64 + nt * 8 + tig * 2;
            atomicAdd(&C[(size_t)r0 * ldc + c],           acc[mt][nt][0]);
            atomicAdd(&C[(size_t)r0 * ldc + c + 1],       acc[mt][nt][1]);
            atomicAdd(&C[(size_t)(r0 + 8) * ldc + c],     acc[mt][nt][2]);
            atomicAdd(&C[(size_t)(r0 + 8) * ldc + c + 1], acc[mt][nt][3]);
        }
    }
}

// ================= slow NN GEMM (register pipeline, cvt/combine epilogues) =================
static constexpr int AS_STRIDE = 20;
static constexpr int A_BUFW = 128 * AS_STRIDE;
static constexpr int B_BUFW = 256 * AS_STRIDE;
static constexpr int GEMM_SMEM_BYTES = (2 * A_BUFW + 2 * B_BUFW) * 4;  // 61440

__global__ void __launch_bounds__(256, 1) gemm_nn_tc(
    const float* __restrict__ A, const float* __restrict__ A2,
    const float* __restrict__ BT, const float* __restrict__ B2T, float b2s,
    const float* __restrict__ bias, const float* __restrict__ bias2, float bias2s,
    float* __restrict__ C, float* __restrict__ Caux, const float* __restrict__ aux,
    int K, int lda, int ldbt, int ldc, int mode,
    int cvtA, int cvtB, int roundC)
{
    extern __shared__ uint32_t sm[];
    uint32_t* AsBuf = sm;
    uint32_t* BsBuf = sm + 2 * A_BUFW;

    const int tid = threadIdx.x, lane = tid & 31, wid = tid >> 5;
    const int wm = wid & 1, wn = wid >> 1;
    const int g = lane >> 2, tig = lane & 3;
    const int bm = blockIdx.y * 128, bn = blockIdx.x * 256;

    float acc[4][8][4] = {};

    const uint32_t smBase = (uint32_t)__cvta_generic_to_shared(sm);
    const uint32_t aAddr0 = smBase + (((wm * 64 + (lane & 15)) * AS_STRIDE + ((lane >> 4) << 2)) << 2);
    const uint32_t bAddr0 = smBase + ((2 * A_BUFW
                          + (wn * 64 + (lane & 7) + ((lane & 16) ? 8 : 0)) * AS_STRIDE
                          + ((lane & 8) ? 4 : 0)) << 2);

    float4 ra[2], rb[4];

    auto ldgAll = [&](int k0) {
        #pragma unroll
        for (int r = 0; r < 2; r++) {
            int row = (r * 256 + tid) >> 2; int kc = ((r * 256 + tid) & 3) << 2;
            float4 v = *(const float4*)(A + (size_t)(bm + row) * lda + k0 + kc);
            if (A2) {
                float4 w = *(const float4*)(A2 + (size_t)(bm + row) * lda + k0 + kc);
                v.x += w.x; v.y += w.y; v.z += w.z; v.w += w.w;
            }
            ra[r] = v;
        }
        #pragma unroll
        for (int r = 0; r < 4; r++) {
            int row = (r * 256 + tid) >> 2; int kc = ((r * 256 + tid) & 3) << 2;
            float4 v = *(const float4*)(BT + (size_t)(bn + row) * ldbt + k0 + kc);
            if (B2T) {
                float4 w = *(const float4*)(B2T + (size_t)(bn + row) * ldbt + k0 + kc);
                v.x += b2s * w.x; v.y += b2s * w.y; v.z += b2s * w.z; v.w += b2s * w.w;
            }
            rb[r] = v;
        }
    };
    auto stsAll = [&](int buf) {
        #pragma unroll
        for (int r = 0; r < 2; r++) {
            int row = (r * 256 + tid) >> 2; int kc = ((r * 256 + tid) & 3) << 2;
            uint32_t* d = &AsBuf[buf * A_BUFW + row * AS_STRIDE + kc];
            if (cvtA) {
                d[0] = f2tf(ra[r].x); d[1] = f2tf(ra[r].y);
                d[2] = f2tf(ra[r].z); d[3] = f2tf(ra[r].w);
            } else {
                *(float4*)d = ra[r];
            }
        }
        #pragma unroll
        for (int r = 0; r < 4; r++) {
            int row = (r * 256 + tid) >> 2; int kc = ((r * 256 + tid) & 3) << 2;
            uint32_t* d = &BsBuf[buf * B_BUFW + row * AS_STRIDE + kc];
            if (cvtB) {
                d[0] = f2tf(rb[r].x); d[1] = f2tf(rb[r].y);
                d[2] = f2tf(rb[r].z); d[3] = f2tf(rb[r].w);
            } else {
                *(float4*)d = rb[r];
            }
        }
    };

    ldgAll(0);
    stsAll(0);
    if (K > 16) ldgAll(16);
    __syncthreads();

    int cur = 0;
    for (int k0 = 0; k0 < K; k0 += 16) {
        if (k0 + 16 < K) stsAll(cur ^ 1);
        if (k0 + 32 < K) ldgAll(k0 + 32);

        const uint32_t aOff = (uint32_t)(cur * A_BUFW * 4);
        const uint32_t bOff = (uint32_t)(cur * B_BUFW * 4);
        #pragma unroll
        for (int ks = 0; ks < 16; ks += 8) {
            uint32_t bq[16];
            #pragma unroll
            for (int nt2 = 0; nt2 < 4; nt2++) {
                uint32_t ad = bAddr0 + bOff + ((nt2 * 16 * AS_STRIDE + ks) << 2);
                LDSM4(bq[nt2 * 4 + 0], bq[nt2 * 4 + 1], bq[nt2 * 4 + 2], bq[nt2 * 4 + 3], ad);
            }
            #pragma unroll
            for (int mt = 0; mt < 4; mt++) {
                uint32_t a0, a1, a2, a3;
                uint32_t ad = aAddr0 + aOff + ((mt * 16 * AS_STRIDE + ks) << 2);
                LDSM4(a0, a1, a2, a3, ad);
                #pragma unroll
                for (int nt = 0; nt < 8; nt++)
                    MMA_TF32(acc[mt][nt], a0, a1, a2, a3, bq[nt * 2], bq[nt * 2 + 1]);
            }
        }
        __syncthreads();
        cur ^= 1;
    }

    #pragma unroll
    for (int mt = 0; mt < 4; mt++) {
        const int r0 = bm + wm * 64 + mt * 16 + g;
        #pragma unroll
        for (int nt = 0; nt < 8; nt++) {
            const int c = bn + wn * 64 + nt * 8 + tig * 2;
            float v0 = acc[mt][nt][0], v1 = acc[mt][nt][1];
            float v2 = acc[mt][nt][2], v3 = acc[mt][nt][3];
            if (bias) {
                float b0v = bias[c], b1v = bias[c + 1];
                if (bias2) { b0v += bias2s * bias2[c]; b1v += bias2s * bias2[c + 1]; }
                v0 += b0v; v1 += b1v; v2 += b0v; v3 += b1v;
            }
            const size_t i0 = (size_t)r0 * ldc + c;
            const size_t i1 = (size_t)(r0 + 8) * ldc + c;
            if (mode == 3) {
                v0 = gelu_f(v0); v1 = gelu_f(v1); v2 = gelu_f(v2); v3 = gelu_f(v3);
            }
            if (roundC) {
                v0 = roundtf(v0); v1 = roundtf(v1); v2 = roundtf(v2); v3 = roundtf(v3);
            }
            *(float2*)&C[i0] = make_float2(v0, v1);
            *(float2*)&C[i1] = make_float2(v2, v3);
        }
    }
    (void)Caux; (void)aux; (void)mode;
}

// ---------------- fused prep ----------------
__device__ void do_transpose32(const float* in, float* out, int R, int C, int bx, int by) {
    __shared__ float t[32][33];
    const int x = threadIdx.x & 31, y = threadIdx.x >> 5;
    const int c0 = bx * 32, r0 = by * 32;
    #pragma unroll
    for (int dy = 0; dy < 32; dy += 8)
        t[y + dy][x] = in[(size_t)(r0 + y + dy) * C + c0 + x];
    __syncthreads();
    #pragma unroll
    for (int dy = 0; dy < 32; dy += 8)
        out[(size_t)(c0 + y + dy) * R + r0 + x] = roundtf(t[x][y + dy]);
}

static constexpr int PREP_BLOCKS = 5159;

__global__ void __launch_bounds__(256) prep_all(
    const float* __restrict__ Wp, const float* __restrict__ Wphi,
    const float* __restrict__ W1, const float* __restrict__ W2,
    const float* __restrict__ Wg, const float* __restrict__ Wpsi,
    const float* __restrict__ Wh, const float* __restrict__ b2,
    const float* __restrict__ gb)
{
    float* S = g_scratch;
    const int b = blockIdx.x, tid = threadIdx.x;
    if (b < 32)        { int lb = b;        do_transpose32(Wp,   S + O_WPT,   128, CU, lb % 8,  lb / 8); }
    else if (b < 96)   { int lb = b - 32;   do_transpose32(Wphi, S + O_WPHIT, CU,  CU, lb % 8,  lb / 8); }
    else if (b < 352)  { int lb = b - 96;   do_transpose32(W1,   S + O_W1T,   CU,  CH, lb % 32, lb / 32); }
    else if (b < 608)  { int lb = b - 352;  do_transpose32(W2,   S + O_W2T,   CH,  CU, lb % 8,  lb / 8); }
    else if (b < 672)  { int lb = b - 608;  do_transpose32(Wg,   S + O_WGT,   CU,  CU, lb % 8,  lb / 8); }
    else if (b < 736)  { int lb = b - 672;  do_transpose32(Wpsi, S + O_WPSIT, CU,  CU, lb % 8,  lb / 8); }
    else if (b < 800)  { int lb = b - 736;  do_transpose32(Wh,   S + O_WHT,   CU,  CU, lb % 8,  lb / 8); }
    else if (b < 1056) { size_t i = (size_t)(b - 800)  * 256 + tid; S[O_WGR + i] = roundtf(Wg[i]); }
    else if (b < 2080) { size_t i = (size_t)(b - 1056) * 256 + tid; S[O_W2R + i] = roundtf(W2[i]); }
    else if (b < 4133) { size_t i = (size_t)(b - 2080) * 256 + tid; S[O_DW1T + i] = 0.f; }
    else if (b < 5158) { size_t i = (size_t)(b - 4133) * 256 + tid; S[O_GT + i] = 0.f; }
    else {
        int n = tid;
        float s = gb[n];
        for (int k = 0; k < CU; k++) s += b2[k] * Wg[(size_t)k * CU + n];
        S[O_ZB + n] = s;
    }
}

// ---------------- other small kernels ----------------
__global__ void transpose_k(const float* __restrict__ in, float* __restrict__ out, int R, int C) {
    do_transpose32(in, out, R, C, blockIdx.x, blockIdx.y);
}

__global__ void shift_k(const float* __restrict__ seq, const float* __restrict__ proj,
                        float* __restrict__ buf_out, float* __restrict__ XR) {
    size_t idx = (size_t)blockIdx.x * 256 + threadIdx.x;
    int u = (int)(idx & (CU - 1));
    int t = (int)((idx >> 8) & (CL - 1));
    int b = (int)(idx >> 15);
    float val = (t < CL - 1) ? seq[(size_t)b * CL * CU + (size_t)(t + 1) * CU + u]
                             : proj[(size_t)b * CU + u];
    buf_out[idx] = val;
    if (t < CL - 1) XR[((size_t)b * (CL - 1) + t) * CU + u] = roundtf(val);
}

__global__ void db2_k(const float* __restrict__ Wg, const float* __restrict__ cdz,
                      float* __restrict__ db2) {
    int j = threadIdx.x;
    float s = 0.f;
    for (int k = 0; k < CU; k++) s += Wg[(size_t)j * CU + k] * cdz[k];
    db2[j] = s;
}

__global__ void colsum_k(const float* __restrict__ A, float* __restrict__ out,
                         int K, int N, int kChunk) {
    __shared__ float sh[8][33];
    const int n = blockIdx.x * 32 + (threadIdx.x & 31);
    const int kl = threadIdx.x >> 5;
    const int kb = blockIdx.y * kChunk;
    const int ke = min(K, kb + kChunk);
    float s = 0.f;
    for (int k = kb + kl; k < ke; k += 8) s += A[(size_t)k * N + n];
    sh[kl][threadIdx.x & 31] = s;
    __syncthreads();
    if (kl == 0) {
        float t = 0.f;
        #pragma unroll
        for (int i = 0; i < 8; i++) t += sh[i][threadIdx.x & 31];
        atomicAdd(&out[n], t);
    }
}

// ---- LN fused, warp-per-row ----
__global__ void __launch_bounds__(256) ln_fused_k(
    const float* __restrict__ z, const float* __restrict__ buf,
    const float* __restrict__ g, const float* __restrict__ bb,
    float* __restrict__ rec, float* __restrict__ dz)
{
    const int wid = threadIdx.x >> 5, lane = threadIdx.x & 31;
    const int row = blockIdx.x * 8 + wid;
    const size_t base = (size_t)row * CU;
    const int yrow = row + (int)((unsigned)row / 127u) + 1;
    const float* zp = z + base;
    const float* yp = buf + (size_t)yrow * CU;

    float v[8], gg[8], bv[8], yv[8];
    #pragma unroll
    for (int i = 0; i < 8; i++) {
        int c = lane + i * 32;
        v[i] = zp[c]; gg[i] = g[c]; bv[i] = bb[c]; yv[i] = yp[c];
    }
    float s = v[0] + v[1] + v[2] + v[3] + v[4] + v[5] + v[6] + v[7];
    #pragma unroll
    for (int o = 16; o; o >>= 1) s += __shfl_xor_sync(0xffffffffu, s, o);
    const float m = s * (1.0f / CU);

    float d[8], s2v = 0.f;
    #pragma unroll
    for (int i = 0; i < 8; i++) { d[i] = v[i] - m; s2v += d[i] * d[i]; }
    #pragma unroll
    for (int o = 16; o; o >>= 1) s2v += __shfl_xor_sync(0xffffffffu, s2v, o);
    const float r = rsqrtf(s2v * (1.0f / CU) + 1e-3f);

    float xh[8], dxh[8], p1 = 0.f, p2 = 0.f;
    #pragma unroll
    for (int i = 0; i < 8; i++) {
        xh[i] = d[i] * r;
        float recv = gg[i] * xh[i] + bv[i];
        rec[base + lane + i * 32] = recv;
        float drec = (recv - yv[i]) * DREC_SCALE;
        dxh[i] = drec * gg[i];
        p1 += dxh[i]; p2 += dxh[i] * xh[i];
    }
    #pragma unroll
    for (int o = 16; o; o >>= 1) {
        p1 += __shfl_xor_sync(0xffffffffu, p1, o);
        p2 += __shfl_xor_sync(0xffffffffu, p2, o);
    }
    const float s1 = p1 * (1.0f / CU), sx = p2 * (1.0f / CU);
    #pragma unroll
    for (int i = 0; i < 8; i++)
        dz[base + lane + i * 32] = roundtf(r * (dxh[i] - s1 - xh[i] * sx));
}

__global__ void contrib_k(const float* __restrict__ rec, float* __restrict__ out) {
    const int b = blockIdx.x, u = threadIdx.x;
    const float* p = rec + (size_t)b * (CL - 1) * CU + u;
    float s = 0.f;
    for (int t = 0; t < CL - 1; t++) s += p[(size_t)t * CU];
    out[(size_t)b * CU + u] = s * (1.0f / (CL - 1));
}

// ---------------- launch ----------------
extern "C" void kernel_launch(void* const* d_in, const int* in_sizes, int n_in,
                              void* d_out, int out_size) {
    const float* inputs = (const float*)d_in[0];
    const float* seq  = (const float*)d_in[2];
    const float* Wp   = (const float*)d_in[3];
    const float* bp   = (const float*)d_in[4];
    const float* Wphi = (const float*)d_in[5];
    const float* bphi = (const float*)d_in[6];
    const float* Wpsi = (const float*)d_in[7];
    const float* bpsi = (const float*)d_in[8];
    const float* W1   = (const float*)d_in[9];
    const float* b1   = (const float*)d_in[10];
    const float* W2   = (const float*)d_in[11];
    const float* b2   = (const float*)d_in[12];
    const float* Wg   = (const float*)d_in[13];
    const float* gb   = (const float*)d_in[14];
    const float* lng  = (const float*)d_in[15];
    const float* lnb  = (const float*)d_in[16];
    const float* Wh   = (const float*)d_in[17];
    const float* hb   = (const float*)d_in[18];

    float* out = (float*)d_out;
    float* buf_out = out + (size_t)CB * CU;

    cudaFuncSetAttribute(gemm_nn_tc,   cudaFuncAttributeMaxDynamicSharedMemorySize, GEMM_SMEM_BYTES);
    cudaFuncSetAttribute(gemm_nn_fast, cudaFuncAttributeMaxDynamicSharedMemorySize, FAST_SMEM_BYTES);
    cudaFuncSetAttribute(gemm_tn_fast, cudaFuncAttributeMaxDynamicSharedMemorySize, TN_SMEM_BYTES);

    float* S = nullptr;
    cudaGetSymbolAddress((void**)&S, g_scratch);
    float *PHI = S + O_PHI, *Z = S + O_Z, *REC = S + O_REC, *DZ = S + O_DZ;
    float *PRE = S + O_PRE, *H = S + O_H;
    float *DW1T = S + O_DW1T, *DW2T = S + O_DW2T, *DB1 = S + O_DB1, *DB2 = S + O_DB2;
    float *WpT = S + O_WPT, *WphiT = S + O_WPHIT, *W1T = S + O_W1T, *W2T = S + O_W2T;
    float *WpsiT = S + O_WPSIT, *WhT = S + O_WHT;
    float *WgR = S + O_WGR, *W2R = S + O_W2R, *WgT = S + O_WGT;
    float *COMBT = S + O_COMBT, *COMB = S + O_COMB, *GT = S + O_GT, *CDZ = S + O_CDZ;
    float *ZB = S + O_ZB;
    float *PROJ = S + O_PROJ, *PSI = S + O_PSI;
    float *HPSI = S + O_HPSI, *EPSI = S + O_EPSI, *CONTRIB = S + O_CONTRIB;
    float *XR = S + O_XR;

    // 0: all prep
    prep_all<<<PREP_BLOCKS, 256>>>(Wp, Wphi, W1, W2, Wg, Wpsi, Wh, b2, gb);

    // 1: proj = inputs @ Wp + bp
    gemm_nn_tc<<<dim3(1, CB / 128), 256, GEMM_SMEM_BYTES>>>(inputs, nullptr, WpT, nullptr, 0.f,
        bp, nullptr, 0.f, PROJ, nullptr, nullptr, 128, 128, 128, CU, 0, 1, 0, 0);

    // 2: shift buffer + rounded X
    shift_k<<<(CB * CL * CU) / 256, 256>>>(seq, PROJ, buf_out, XR);

    // 3 (ncu-profiled): phi = XR @ Wphi + bphi (rounded output)
    gemm_nn_fast<<<dim3(CU / 128, CNR / 128), 128, FAST_SMEM_BYTES>>>(XR, WphiT,
        bphi, PHI, nullptr, nullptr, nullptr, CU, CU, CU, CU, 0, 1);

    // 4: COMB = W2 @ Wg [1024,256], rounded
    gemm_nn_tc<<<dim3(1, CH / 128), 256, GEMM_SMEM_BYTES>>>(W2R, nullptr, WgT, nullptr, 0.f,
        nullptr, nullptr, 0.f, COMB, nullptr, nullptr, CU, CU, CU, CU, 0, 0, 0, 1);

    // 5: COMBT = COMB^T
    transpose_k<<<dim3(CU / 32, CH / 32), dim3(256)>>>(COMB, COMBT, CH, CU);

    // pre = phi@W1+b1 ; H = gelu(pre) rounded, PRE := dgelu(pre)
    gemm_nn_fast<<<dim3(CH / 128, CNR / 128), 128, FAST_SMEM_BYTES>>>(PHI, W1T,
        b1, H, PRE, nullptr, nullptr, CU, CU, CU, CH, 1, 1);

    // z = H @ (W2@Wg) + (b2@Wg + gb)
    gemm_nn_fast<<<dim3(CU / 128, CNR / 128), 128, FAST_SMEM_BYTES>>>(H, COMBT,
        ZB, Z, nullptr, nullptr, nullptr, CH, CH, CH, CU, 0, 0);

    // rec = LN(z); dz = LN_bwd(...) rounded
    ln_fused_k<<<CNR / 8, 256>>>(Z, buf_out, lng, lnb, REC, DZ);

    // cdz = colsum(dz); db2 = Wg @ cdz
    colsum_k<<<dim3(CU / 32, 32), 256>>>(DZ, CDZ, CNR, CU, 2032);
    db2_k<<<1, 256>>>(Wg, CDZ, DB2);

    // GT = H^T @ dz  [1024,256]  (staged TN, 37 splits x 1760)
    gemm_tn_fast<<<dim3(CU / 128, CH / 128, 37), 128, TN_SMEM_BYTES>>>(
        H, DZ, GT, CNR, CH, CU, CU, 1760);

    // dW2T = Wg @ GT^T  [256,1024]
    gemm_nn_tc<<<dim3(CH / 256, CU / 128), 256, GEMM_SMEM_BYTES>>>(WgR, nullptr, GT, nullptr, 0.f,
        nullptr, nullptr, 0.f, DW2T, nullptr, nullptr, CU, CU, CU, CH, 0, 0, 1, 0);

    // dpre = (dz @ COMB^T) * stored-dgelu + db1 colsum; rounded, in-place over PRE
    gemm_nn_fast<<<dim3(CH / 128, CNR / 128), 128, FAST_SMEM_BYTES>>>(DZ, COMB,
        nullptr, PRE, nullptr, PRE, DB1, CU, CU, CU, CH, 2, 1);

    // dW1T = dpre^T @ phi  (staged TN)
    gemm_tn_fast<<<dim3(CU / 128, CH / 128, 37), 128, TN_SMEM_BYTES>>>(
        PRE, PHI, DW1T, CNR, CH, CU, CU, 1760);

    contrib_k<<<CB, 256>>>(REC, CONTRIB);

    // psi = proj @ Wpsi + bpsi  (rounded output)
    gemm_nn_tc<<<dim3(1, CB / 128), 256, GEMM_SMEM_BYTES>>>(PROJ, nullptr, WpsiT, nullptr, 0.f,
        bpsi, nullptr, 0.f, PSI, nullptr, nullptr, CU, CU, CU, CU, 0, 1, 0, 1);

    // hpsi = gelu(psi @ (W1 - lr dW1) + (b1 - lr db1))
    gemm_nn_tc<<<dim3(CH / 256, CB / 128), 256, GEMM_SMEM_BYTES>>>(PSI, nullptr, W1T, DW1T, -LR,
        b1, DB1, -LR, HPSI, nullptr, nullptr, CU, CU, CU, CH, 3, 0, 1, 1);

    // epsi = hpsi @ (W2 - lr dW2) + (b2 - lr db2)
    gemm_nn_tc<<<dim3(1, CB / 128), 256, GEMM_SMEM_BYTES>>>(HPSI, nullptr, W2T, DW2T, -LR,
        b2, DB2, -LR, EPSI, nullptr, nullptr, CH, CH, CH, CU, 0, 0, 1, 0);

    // out = (epsi + contrib) @ Wh + h_bias
    gemm_nn_tc<<<dim3(1, CB / 128), 256, GEMM_SMEM_BYTES>>>(EPSI, CONTRIB, WhT, nullptr, 0.f,
        hb, nullptr, 0.f, out, nullptr, nullptr, CU, CU, CU, CU, 0, 1, 0, 0);

    (void)in_sizes; (void)n_in; (void)out_size;
}

// round 16
// speedup vs baseline: 1.3448x; 1.0326x over previous
#include <cuda_runtime.h>
#include <math.h>
#include <stdint.h>

// ---------------- problem constants ----------------
#define CU   256
#define CL   128
#define CB   512
#define CNR  65024               // CB*(CL-1)
#define CH   1024                // 4*U

static constexpr float LR = 0.01f;
static constexpr float DREC_SCALE = 2.0f / (65024.0f * 256.0f);

// ---------------- scratch ----------------
static constexpr size_t SZ_NU = (size_t)CNR * CU;
static constexpr size_t SZ_NH = (size_t)CNR * CH;

static constexpr size_t O_PHI    = 0;
static constexpr size_t O_Z      = O_PHI + SZ_NU;
static constexpr size_t O_REC    = O_Z   + SZ_NU;
static constexpr size_t O_DZ     = O_REC + SZ_NU;
static constexpr size_t O_PRE    = O_DZ  + SZ_NU;   // holds dgelu(pre), then dpre in-place
static constexpr size_t O_H      = O_PRE + SZ_NH;
static constexpr size_t O_DW1T   = O_H   + SZ_NH;                 // [1024,256]
static constexpr size_t O_DW2T   = O_DW1T + (size_t)CH*CU;        // [256,1024]
static constexpr size_t O_DB1    = O_DW2T + (size_t)CU*CH;
static constexpr size_t O_DB2    = O_DB1 + CH;
static constexpr size_t O_WPT    = O_DB2 + CU;                    // [256,128]
static constexpr size_t O_WPHIT  = O_WPT + (size_t)CU*128;
static constexpr size_t O_W1T    = O_WPHIT + (size_t)CU*CU;       // [1024,256]
static constexpr size_t O_W2T    = O_W1T + (size_t)CH*CU;         // [256,1024]
static constexpr size_t O_WGT    = O_W2T + (size_t)CU*CH;
static constexpr size_t O_WPSIT  = O_WGT + (size_t)CU*CU;
static constexpr size_t O_WHT    = O_WPSIT + (size_t)CU*CU;
static constexpr size_t O_WGR    = O_WHT + (size_t)CU*CU;         // rounded Wg
static constexpr size_t O_W2R    = O_WGR + (size_t)CU*CU;         // rounded W2
static constexpr size_t O_COMBT  = O_W2R + (size_t)CH*CU;         // (W2@Wg)^T [256,1024]
static constexpr size_t O_COMB   = O_COMBT + (size_t)CU*CH;       // W2@Wg [1024,256]
static constexpr size_t O_GT     = O_COMB + (size_t)CH*CU;        // H^T@dz [1024,256]
static constexpr size_t O_CDZ    = O_GT + (size_t)CH*CU;          // colsum(dz) [256]
static constexpr size_t O_ZB     = O_CDZ + CU;
static constexpr size_t O_PROJ   = O_ZB + CU;
static constexpr size_t O_PSI    = O_PROJ + (size_t)CB*CU;
static constexpr size_t O_HPSI   = O_PSI  + (size_t)CB*CU;
static constexpr size_t O_EPSI   = O_HPSI + (size_t)CB*CH;
static constexpr size_t O_CONTRIB= O_EPSI + (size_t)CB*CU;
static constexpr size_t O_XR     = O_CONTRIB + (size_t)CB*CU;     // rounded X [CNR,256]
static constexpr size_t O_END    = O_XR + SZ_NU;

__device__ float g_scratch[O_END];

// ---------------- helpers ----------------
__device__ __forceinline__ float gelu_f(float x) {
    return 0.5f * x * (1.0f + erff(x * 0.7071067811865476f));
}
__device__ __forceinline__ void gelu_both(float x, float& gv, float& dv) {
    float cdf = 0.5f * (1.0f + erff(x * 0.7071067811865476f));
    gv = x * cdf;
    dv = cdf + x * 0.3989422804014327f * expf(-0.5f * x * x);
}
__device__ __forceinline__ uint32_t f2tf(float x) {
    uint32_t r; asm("cvt.rna.tf32.f32 %0, %1;" : "=r"(r) : "f"(x)); return r;
}
__device__ __forceinline__ float roundtf(float x) { return __uint_as_float(f2tf(x)); }

#define LDSM4(r0,r1,r2,r3,addr) \
    asm volatile("ldmatrix.sync.aligned.m8n8.x4.shared.b16 {%0,%1,%2,%3}, [%4];" \
                 : "=r"(r0),"=r"(r1),"=r"(r2),"=r"(r3) : "r"(addr))

#define MMA_TF32(c,a0,a1,a2,a3,b0,b1) \
    asm volatile("mma.sync.aligned.m16n8k8.row.col.f32.tf32.tf32.f32 " \
                 "{%0,%1,%2,%3},{%4,%5,%6,%7},{%8,%9},{%0,%1,%2,%3};" \
                 : "+f"(c[0]),"+f"(c[1]),"+f"(c[2]),"+f"(c[3]) \
                 : "r"(a0),"r"(a1),"r"(a2),"r"(a3),"r"(b0),"r"(b1))

#define MMA_TF32F(c,a0,a1,a2,a3,b0,b1) \
    asm volatile("mma.sync.aligned.m16n8k8.row.col.f32.tf32.tf32.f32 " \
                 "{%0,%1,%2,%3},{%4,%5,%6,%7},{%8,%9},{%0,%1,%2,%3};" \
                 : "+f"(c[0]),"+f"(c[1]),"+f"(c[2]),"+f"(c[3]) \
                 : "r"(__float_as_uint(a0)),"r"(__float_as_uint(a1)), \
                   "r"(__float_as_uint(a2)),"r"(__float_as_uint(a3)), \
                   "r"(__float_as_uint(b0)),"r"(__float_as_uint(b1)))

#define CP16(smaddr, gptr) \
    asm volatile("cp.async.cg.shared.global [%0], [%1], 16;" :: "r"(smaddr), "l"(gptr))

// ===== FAST NN GEMM: 128 threads, 4 warps (2x2), tile 128x128, 3-stage, 2 CTAs/SM =====
// Single barrier per K-chunk: stage issued post-barrier reuses the slot consumed
// in the previous iteration, which the barrier fences.
static constexpr int FSTRIDE = 36;
static constexpr int FA_STAGE = 128 * FSTRIDE;
static constexpr int FB_STAGE = 128 * FSTRIDE;
static constexpr int STAGE_W  = FA_STAGE + FB_STAGE;      // 9216 words
static constexpr int FAST_SMEM_BYTES = 3 * STAGE_W * 4;   // 110592 B -> 2 CTAs/SM

__global__ void __launch_bounds__(128, 2) gemm_nn_fast(
    const float* __restrict__ A, const float* __restrict__ BT,
    const float* __restrict__ bias,
    float* __restrict__ C, float* __restrict__ Caux, const float* __restrict__ aux,
    float* __restrict__ colsum_out,
    int K, int lda, int ldbt, int ldc, int mode, int roundC)
{
    extern __shared__ uint32_t sm[];
    const int tid = threadIdx.x, lane = tid & 31, wid = tid >> 5;
    const int wm = wid & 1, wn = (wid >> 1) & 1;
    const int g = lane >> 2, tig = lane & 3;
    const int bm = blockIdx.y * 128, bn = blockIdx.x * 128;

    float acc[4][8][4] = {};

    const uint32_t smBase = (uint32_t)__cvta_generic_to_shared(sm);
    const int aRow = (wm * 64 + (lane & 15)) * FSTRIDE + ((lane & 16) ? 4 : 0);
    const int bRow = FA_STAGE + (wn * 64 + (lane & 7) + ((lane & 16) ? 8 : 0)) * FSTRIDE
                   + ((lane & 8) ? 4 : 0);

    const int nch = K / 32;

    auto issueStage = [&](int ci) {
        const int st = ci - (ci / 3) * 3;
        uint32_t sa = smBase + (uint32_t)(st * STAGE_W * 4);
        const int k0 = ci * 32;
        #pragma unroll
        for (int t = 0; t < 8; t++) {
            int id = t * 128 + tid;
            int row = id >> 3, kc = (id & 7) << 2;
            uint32_t d = sa + (uint32_t)((row * FSTRIDE + kc) << 2);
            CP16(d, A + (size_t)(bm + row) * lda + k0 + kc);
        }
        uint32_t sb = sa + (uint32_t)(FA_STAGE * 4);
        #pragma unroll
        for (int t = 0; t < 8; t++) {
            int id = t * 128 + tid;
            int row = id >> 3, kc = (id & 7) << 2;
            uint32_t d = sb + (uint32_t)((row * FSTRIDE + kc) << 2);
            CP16(d, BT + (size_t)(bn + row) * ldbt + k0 + kc);
        }
        asm volatile("cp.async.commit_group;");
    };

    issueStage(0);
    if (nch > 1) issueStage(1);

    for (int ci = 0; ci < nch; ci++) {
        if (ci + 1 < nch) asm volatile("cp.async.wait_group 1;");
        else              asm volatile("cp.async.wait_group 0;");
        __syncthreads();                      // single barrier per chunk
        if (ci + 2 < nch) issueStage(ci + 2); // writes slot (ci-1)%3, fenced above

        const int st = ci - (ci / 3) * 3;
        const uint32_t base = smBase + (uint32_t)(st * STAGE_W * 4);
        #pragma unroll
        for (int s = 0; s < 4; s++) {
            uint32_t bq[16];
            #pragma unroll
            for (int nt2 = 0; nt2 < 4; nt2++) {
                uint32_t ad = base + (uint32_t)((bRow + nt2 * 16 * FSTRIDE + s * 8) << 2);
                LDSM4(bq[nt2 * 4 + 0], bq[nt2 * 4 + 1], bq[nt2 * 4 + 2], bq[nt2 * 4 + 3], ad);
            }
            #pragma unroll
            for (int mt = 0; mt < 4; mt++) {
                uint32_t a0, a1, a2, a3;
                uint32_t ad = base + (uint32_t)((aRow + mt * 16 * FSTRIDE + s * 8) << 2);
                LDSM4(a0, a1, a2, a3, ad);
                #pragma unroll
                for (int nt = 0; nt < 8; nt++)
                    MMA_TF32(acc[mt][nt], a0, a1, a2, a3, bq[nt * 2], bq[nt * 2 + 1]);
            }
        }
    }

    // ---------------- epilogue ----------------
    float csum[8][2];
    #pragma unroll
    for (int nt = 0; nt < 8; nt++) { csum[nt][0] = 0.f; csum[nt][1] = 0.f; }

    #pragma unroll
    for (int mt = 0; mt < 4; mt++) {
        const int r0 = bm + wm * 64 + mt * 16 + g;
        #pragma unroll
        for (int nt = 0; nt < 8; nt++) {
            const int c = bn + wn * 64 + nt * 8 + tig * 2;
            float v0 = acc[mt][nt][0], v1 = acc[mt][nt][1];
            float v2 = acc[mt][nt][2], v3 = acc[mt][nt][3];
            if (bias) {
                float b0v = bias[c], b1v = bias[c + 1];
                v0 += b0v; v1 += b1v; v2 += b0v; v3 += b1v;
            }
            const size_t i0 = (size_t)r0 * ldc + c;
            const size_t i1 = (size_t)(r0 + 8) * ldc + c;
            if (mode == 1) {
                float d0, d1, d2, d3, g0, g1, g2, g3;
                gelu_both(v0, g0, d0); gelu_both(v1, g1, d1);
                gelu_both(v2, g2, d2); gelu_both(v3, g3, d3);
                *(float2*)&Caux[i0] = make_float2(d0, d1);
                *(float2*)&Caux[i1] = make_float2(d2, d3);
                v0 = g0; v1 = g1; v2 = g2; v3 = g3;
            } else if (mode == 2) {
                float2 x0 = *(const float2*)&aux[i0];
                float2 x1 = *(const float2*)&aux[i1];
                v0 *= x0.x; v1 *= x0.y; v2 *= x1.x; v3 *= x1.y;
            }
            if (roundC) {
                v0 = roundtf(v0); v1 = roundtf(v1); v2 = roundtf(v2); v3 = roundtf(v3);
            }
            *(float2*)&C[i0] = make_float2(v0, v1);
            *(float2*)&C[i1] = make_float2(v2, v3);
            if (colsum_out) { csum[nt][0] += v0 + v2; csum[nt][1] += v1 + v3; }
        }
    }

    if (colsum_out) {
        __syncthreads();
        float* cs = (float*)sm;
        cs[tid] = 0.f;
        __syncthreads();
        #pragma unroll
        for (int nt = 0; nt < 8; nt++) {
            #pragma unroll
            for (int j = 0; j < 2; j++) {
                float v = csum[nt][j];
                v += __shfl_xor_sync(0xffffffffu, v, 4);
                v += __shfl_xor_sync(0xffffffffu, v, 8);
                v += __shfl_xor_sync(0xffffffffu, v, 16);
                if (g == 0) atomicAdd(&cs[wn * 64 + nt * 8 + tig * 2 + j], v);
            }
        }
        __syncthreads();
        atomicAdd(&colsum_out[bn + tid], cs[tid]);
    }
}

// ===== FAST TN split-K: staged smem, direct-LDS frags, single barrier/chunk =====
static constexpr int TSTRIDE  = 132;
static constexpr int TA_STAGE = 32 * TSTRIDE;
static constexpr int TSTAGE_W = 2 * TA_STAGE;
static constexpr int TN_SMEM_BYTES = 3 * TSTAGE_W * 4;    // 101376 B -> 2 CTAs/SM

__global__ void __launch_bounds__(128, 2) gemm_tn_fast(
    const float* __restrict__ A, const float* __restrict__ B, float* __restrict__ C,
    int K, int lda, int ldb, int ldc, int kChunk)
{
    extern __shared__ float smf[];
    const int tid = threadIdx.x, lane = tid & 31, wid = tid >> 5;
    const int wm = wid & 1, wn = (wid >> 1) & 1;
    const int g = lane >> 2, tig = lane & 3;
    const int bm = blockIdx.y * 128, bn = blockIdx.x * 128;
    const int kb = blockIdx.z * kChunk;
    const int ke = min(K, kb + kChunk);
    const int nch = (ke - kb) >> 5;

    float acc[4][8][4] = {};

    const uint32_t smBase = (uint32_t)__cvta_generic_to_shared(smf);

    auto issueStage = [&](int ci) {
        const int st = ci - (ci / 3) * 3;
        const int k0 = kb + ci * 32;
        uint32_t sa = smBase + (uint32_t)(st * TSTAGE_W * 4);
        #pragma unroll
        for (int t = 0; t < 8; t++) {
            int id = t * 128 + tid;
            int kk = id >> 5, mg = id & 31;
            uint32_t d = sa + (uint32_t)((kk * TSTRIDE + mg * 4) << 2);
            CP16(d, A + (size_t)(k0 + kk) * lda + bm + mg * 4);
        }
        uint32_t sb = sa + (uint32_t)(TA_STAGE * 4);
        #pragma unroll
        for (int t = 0; t < 8; t++) {
            int id = t * 128 + tid;
            int kk = id >> 5, mg = id & 31;
            uint32_t d = sb + (uint32_t)((kk * TSTRIDE + mg * 4) << 2);
            CP16(d, B + (size_t)(k0 + kk) * ldb + bn + mg * 4);
        }
        asm volatile("cp.async.commit_group;");
    };

    issueStage(0);
    if (nch > 1) issueStage(1);

    for (int ci = 0; ci < nch; ci++) {
        if (ci + 1 < nch) asm volatile("cp.async.wait_group 1;");
        else              asm volatile("cp.async.wait_group 0;");
        __syncthreads();
        if (ci + 2 < nch) issueStage(ci + 2);

        const int st = ci - (ci / 3) * 3;
        const float* As = smf + st * TSTAGE_W;
        const float* Bs = As + TA_STAGE;
        #pragma unroll
        for (int s = 0; s < 4; s++) {
            const int kr0 = s * 8 + tig;
            const float* a_lo = As + kr0 * TSTRIDE;
            const float* a_hi = As + (kr0 + 4) * TSTRIDE;
            const float* b_lo = Bs + kr0 * TSTRIDE;
            const float* b_hi = Bs + (kr0 + 4) * TSTRIDE;

            float bq[8][2];
            #pragma unroll
            for (int nt = 0; nt < 8; nt++) {
                const int nb = wn * 64 + nt * 8 + g;
                bq[nt][0] = b_lo[nb];
                bq[nt][1] = b_hi[nb];
            }
            #pragma unroll
            for (int mt = 0; mt < 4; mt++) {
                const int mb = wm * 64 + mt * 16 + g;
                float a0 = a_lo[mb], a1 = a_lo[mb + 8];
                float a2 = a_hi[mb], a3 = a_hi[mb + 8];
                #pragma unroll
                for (int nt = 0; nt < 8; nt++)
                    MMA_TF32F(acc[mt][nt], a0, a1, a2, a3, bq[nt][0], bq[nt][1]);
            }
        }
    }

    #pragma unroll
    for (int mt = 0; mt < 4; mt++) {
        const int r0 = bm + wm * 64 + mt * 16 + g;
        #pragma unroll
        for (int nt = 0; nt < 8; nt++) {
            const int c = bn + wn * 64 + nt * 8 + tig * 2;
            atomicAdd(&C[(size_t)r0 * ldc + c],           acc[mt][nt][0]);
            atomicAdd(&C[(size_t)r0 * ldc + c + 1],       acc[mt][nt][1]);
            atomicAdd(&C[(size_t)(r0 + 8) * ldc + c],     acc[mt][nt][2]);
            atomicAdd(&C[(size_t)(r0 + 8) * ldc + c + 1], acc[mt][nt][3]);
        }
    }
}

// ================= slow NN GEMM (register pipeline, cvt/combine epilogues) =================
static constexpr int AS_STRIDE = 20;
static constexpr int A_BUFW = 128 * AS_STRIDE;
static constexpr int B_BUFW = 256 * AS_STRIDE;
static constexpr int GEMM_SMEM_BYTES = (2 * A_BUFW + 2 * B_BUFW) * 4;  // 61440

__global__ void __launch_bounds__(256, 1) gemm_nn_tc(
    const float* __restrict__ A, const float* __restrict__ A2,
    const float* __restrict__ BT, const float* __restrict__ B2T, float b2s,
    const float* __restrict__ bias, const float* __restrict__ bias2, float bias2s,
    float* __restrict__ C, float* __restrict__ Caux, const float* __restrict__ aux,
    int K, int lda, int ldbt, int ldc, int mode,
    int cvtA, int cvtB, int roundC)
{
    extern __shared__ uint32_t sm[];
    uint32_t* AsBuf = sm;
    uint32_t* BsBuf = sm + 2 * A_BUFW;

    const int tid = threadIdx.x, lane = tid & 31, wid = tid >> 5;
    const int wm = wid & 1, wn = wid >> 1;
    const int g = lane >> 2, tig = lane & 3;
    const int bm = blockIdx.y * 128, bn = blockIdx.x * 256;

    float acc[4][8][4] = {};

    const uint32_t smBase = (uint32_t)__cvta_generic_to_shared(sm);
    const uint32_t aAddr0 = smBase + (((wm * 64 + (lane & 15)) * AS_STRIDE + ((lane >> 4) << 2)) << 2);
    const uint32_t bAddr0 = smBase + ((2 * A_BUFW
                          + (wn * 64 + (lane & 7) + ((lane & 16) ? 8 : 0)) * AS_STRIDE
                          + ((lane & 8) ? 4 : 0)) << 2);

    float4 ra[2], rb[4];

    auto ldgAll = [&](int k0) {
        #pragma unroll
        for (int r = 0; r < 2; r++) {
            int row = (r * 256 + tid) >> 2; int kc = ((r * 256 + tid) & 3) << 2;
            float4 v = *(const float4*)(A + (size_t)(bm + row) * lda + k0 + kc);
            if (A2) {
                float4 w = *(const float4*)(A2 + (size_t)(bm + row) * lda + k0 + kc);
                v.x += w.x; v.y += w.y; v.z += w.z; v.w += w.w;
            }
            ra[r] = v;
        }
        #pragma unroll
        for (int r = 0; r < 4; r++) {
            int row = (r * 256 + tid) >> 2; int kc = ((r * 256 + tid) & 3) << 2;
            float4 v = *(const float4*)(BT + (size_t)(bn + row) * ldbt + k0 + kc);
            if (B2T) {
                float4 w = *(const float4*)(B2T + (size_t)(bn + row) * ldbt + k0 + kc);
                v.x += b2s * w.x; v.y += b2s * w.y; v.z += b2s * w.z; v.w += b2s * w.w;
            }
            rb[r] = v;
        }
    };
    auto stsAll = [&](int buf) {
        #pragma unroll
        for (int r = 0; r < 2; r++) {
            int row = (r * 256 + tid) >> 2; int kc = ((r * 256 + tid) & 3) << 2;
            uint32_t* d = &AsBuf[buf * A_BUFW + row * AS_STRIDE + kc];
            if (cvtA) {
                d[0] = f2tf(ra[r].x); d[1] = f2tf(ra[r].y);
                d[2] = f2tf(ra[r].z); d[3] = f2tf(ra[r].w);
            } else {
                *(float4*)d = ra[r];
            }
        }
        #pragma unroll
        for (int r = 0; r < 4; r++) {
            int row = (r * 256 + tid) >> 2; int kc = ((r * 256 + tid) & 3) << 2;
            uint32_t* d = &BsBuf[buf * B_BUFW + row * AS_STRIDE + kc];
            if (cvtB) {
                d[0] = f2tf(rb[r].x); d[1] = f2tf(rb[r].y);
                d[2] = f2tf(rb[r].z); d[3] = f2tf(rb[r].w);
            } else {
                *(float4*)d = rb[r];
            }
        }
    };

    ldgAll(0);
    stsAll(0);
    if (K > 16) ldgAll(16);
    __syncthreads();

    int cur = 0;
    for (int k0 = 0; k0 < K; k0 += 16) {
        if (k0 + 16 < K) stsAll(cur ^ 1);
        if (k0 + 32 < K) ldgAll(k0 + 32);

        const uint32_t aOff = (uint32_t)(cur * A_BUFW * 4);
        const uint32_t bOff = (uint32_t)(cur * B_BUFW * 4);
        #pragma unroll
        for (int ks = 0; ks < 16; ks += 8) {
            uint32_t bq[16];
            #pragma unroll
            for (int nt2 = 0; nt2 < 4; nt2++) {
                uint32_t ad = bAddr0 + bOff + ((nt2 * 16 * AS_STRIDE + ks) << 2);
                LDSM4(bq[nt2 * 4 + 0], bq[nt2 * 4 + 1], bq[nt2 * 4 + 2], bq[nt2 * 4 + 3], ad);
            }
            #pragma unroll
            for (int mt = 0; mt < 4; mt++) {
                uint32_t a0, a1, a2, a3;
                uint32_t ad = aAddr0 + aOff + ((mt * 16 * AS_STRIDE + ks) << 2);
                LDSM4(a0, a1, a2, a3, ad);
                #pragma unroll
                for (int nt = 0; nt < 8; nt++)
                    MMA_TF32(acc[mt][nt], a0, a1, a2, a3, bq[nt * 2], bq[nt * 2 + 1]);
            }
        }
        __syncthreads();
        cur ^= 1;
    }

    #pragma unroll
    for (int mt = 0; mt < 4; mt++) {
        const int r0 = bm + wm * 64 + mt * 16 + g;
        #pragma unroll
        for (int nt = 0; nt < 8; nt++) {
            const int c = bn + wn * 64 + nt * 8 + tig * 2;
            float v0 = acc[mt][nt][0], v1 = acc[mt][nt][1];
            float v2 = acc[mt][nt][2], v3 = acc[mt][nt][3];
            if (bias) {
                float b0v = bias[c], b1v = bias[c + 1];
                if (bias2) { b0v += bias2s * bias2[c]; b1v += bias2s * bias2[c + 1]; }
                v0 += b0v; v1 += b1v; v2 += b0v; v3 += b1v;
            }
            const size_t i0 = (size_t)r0 * ldc + c;
            const size_t i1 = (size_t)(r0 + 8) * ldc + c;
            if (mode == 3) {
                v0 = gelu_f(v0); v1 = gelu_f(v1); v2 = gelu_f(v2); v3 = gelu_f(v3);
            }
            if (roundC) {
                v0 = roundtf(v0); v1 = roundtf(v1); v2 = roundtf(v2); v3 = roundtf(v3);
            }
            *(float2*)&C[i0] = make_float2(v0, v1);
            *(float2*)&C[i1] = make_float2(v2, v3);
        }
    }
    (void)Caux; (void)aux; (void)mode;
}

// ---------------- fused prep ----------------
__device__ void do_transpose32(const float* in, float* out, int R, int C, int bx, int by) {
    __shared__ float t[32][33];
    const int x = threadIdx.x & 31, y = threadIdx.x >> 5;
    const int c0 = bx * 32, r0 = by * 32;
    #pragma unroll
    for (int dy = 0; dy < 32; dy += 8)
        t[y + dy][x] = in[(size_t)(r0 + y + dy) * C + c0 + x];
    __syncthreads();
    #pragma unroll
    for (int dy = 0; dy < 32; dy += 8)
        out[(size_t)(c0 + y + dy) * R + r0 + x] = roundtf(t[x][y + dy]);
}

static constexpr int PREP_BLOCKS = 5159;

__global__ void __launch_bounds__(256) prep_all(
    const float* __restrict__ Wp, const float* __restrict__ Wphi,
    const float* __restrict__ W1, const float* __restrict__ W2,
    const float* __restrict__ Wg, const float* __restrict__ Wpsi,
    const float* __restrict__ Wh, const float* __restrict__ b2,
    const float* __restrict__ gb)
{
    float* S = g_scratch;
    const int b = blockIdx.x, tid = threadIdx.x;
    if (b < 32)        { int lb = b;        do_transpose32(Wp,   S + O_WPT,   128, CU, lb % 8,  lb / 8); }
    else if (b < 96)   { int lb = b - 32;   do_transpose32(Wphi, S + O_WPHIT, CU,  CU, lb % 8,  lb / 8); }
    else if (b < 352)  { int lb = b - 96;   do_transpose32(W1,   S + O_W1T,   CU,  CH, lb % 32, lb / 32); }
    else if (b < 608)  { int lb = b - 352;  do_transpose32(W2,   S + O_W2T,   CH,  CU, lb % 8,  lb / 8); }
    else if (b < 672)  { int lb = b - 608;  do_transpose32(Wg,   S + O_WGT,   CU,  CU, lb % 8,  lb / 8); }
    else if (b < 736)  { int lb = b - 672;  do_transpose32(Wpsi, S + O_WPSIT, CU,  CU, lb % 8,  lb / 8); }
    else if (b < 800)  { int lb = b - 736;  do_transpose32(Wh,   S + O_WHT,   CU,  CU, lb % 8,  lb / 8); }
    else if (b < 1056) { size_t i = (size_t)(b - 800)  * 256 + tid; S[O_WGR + i] = roundtf(Wg[i]); }
    else if (b < 2080) { size_t i = (size_t)(b - 1056) * 256 + tid; S[O_W2R + i] = roundtf(W2[i]); }
    else if (b < 4133) { size_t i = (size_t)(b - 2080) * 256 + tid; S[O_DW1T + i] = 0.f; }
    else if (b < 5158) { size_t i = (size_t)(b - 4133) * 256 + tid; S[O_GT + i] = 0.f; }
    else {
        int n = tid;
        float s = gb[n];
        for (int k = 0; k < CU; k++) s += b2[k] * Wg[(size_t)k * CU + n];
        S[O_ZB + n] = s;
    }
}

// ---------------- other small kernels ----------------
__global__ void transpose_k(const float* __restrict__ in, float* __restrict__ out, int R, int C) {
    do_transpose32(in, out, R, C, blockIdx.x, blockIdx.y);
}

// shift: float4-vectorized (CU=256 divisible by 4; gather map unchanged)
__global__ void shift_k(const float4* __restrict__ seq4, const float4* __restrict__ proj4,
                        float4* __restrict__ buf4, float4* __restrict__ XR4) {
    size_t idx = (size_t)blockIdx.x * 256 + threadIdx.x;   // over CB*CL*64
    int u4 = (int)(idx & 63);
    int t  = (int)((idx >> 6) & (CL - 1));
    int b  = (int)(idx >> 13);
    float4 val = (t < CL - 1) ? seq4[(size_t)b * CL * 64 + (size_t)(t + 1) * 64 + u4]
                              : proj4[(size_t)b * 64 + u4];
    buf4[idx] = val;
    if (t < CL - 1) {
        float4 r;
        r.x = roundtf(val.x); r.y = roundtf(val.y);
        r.z = roundtf(val.z); r.w = roundtf(val.w);
        XR4[((size_t)b * (CL - 1) + t) * 64 + u4] = r;
    }
}

__global__ void db2_k(const float* __restrict__ Wg, const float* __restrict__ cdz,
                      float* __restrict__ db2) {
    int j = threadIdx.x;
    float s = 0.f;
    for (int k = 0; k < CU; k++) s += Wg[(size_t)j * CU + k] * cdz[k];
    db2[j] = s;
}

__global__ void colsum_k(const float* __restrict__ A, float* __restrict__ out,
                         int K, int N, int kChunk) {
    __shared__ float sh[8][33];
    const int n = blockIdx.x * 32 + (threadIdx.x & 31);
    const int kl = threadIdx.x >> 5;
    const int kb = blockIdx.y * kChunk;
    const int ke = min(K, kb + kChunk);
    float s = 0.f;
    for (int k = kb + kl; k < ke; k += 8) s += A[(size_t)k * N + n];
    sh[kl][threadIdx.x & 31] = s;
    __syncthreads();
    if (kl == 0) {
        float t = 0.f;
        #pragma unroll
        for (int i = 0; i < 8; i++) t += sh[i][threadIdx.x & 31];
        atomicAdd(&out[n], t);
    }
}

// ---- LN fused, warp-per-row ----
__global__ void __launch_bounds__(256) ln_fused_k(
    const float* __restrict__ z, const float* __restrict__ buf,
    const float* __restrict__ g, const float* __restrict__ bb,
    float* __restrict__ rec, float* __restrict__ dz)
{
    const int wid = threadIdx.x >> 5, lane = threadIdx.x & 31;
    const int row = blockIdx.x * 8 + wid;
    const size_t base = (size_t)row * CU;
    const int yrow = row + (int)((unsigned)row / 127u) + 1;
    const float* zp = z + base;
    const float* yp = buf + (size_t)yrow * CU;

    float v[8], gg[8], bv[8], yv[8];
    #pragma unroll
    for (int i = 0; i < 8; i++) {
        int c = lane + i * 32;
        v[i] = zp[c]; gg[i] = g[c]; bv[i] = bb[c]; yv[i] = yp[c];
    }
    float s = v[0] + v[1] + v[2] + v[3] + v[4] + v[5] + v[6] + v[7];
    #pragma unroll
    for (int o = 16; o; o >>= 1) s += __shfl_xor_sync(0xffffffffu, s, o);
    const float m = s * (1.0f / CU);

    float d[8], s2v = 0.f;
    #pragma unroll
    for (int i = 0; i < 8; i++) { d[i] = v[i] - m; s2v += d[i] * d[i]; }
    #pragma unroll
    for (int o = 16; o; o >>= 1) s2v += __shfl_xor_sync(0xffffffffu, s2v, o);
    const float r = rsqrtf(s2v * (1.0f / CU) + 1e-3f);

    float xh[8], dxh[8], p1 = 0.f, p2 = 0.f;
    #pragma unroll
    for (int i = 0; i < 8; i++) {
        xh[i] = d[i] * r;
        float recv = gg[i] * xh[i] + bv[i];
        rec[base + lane + i * 32] = recv;
        float drec = (recv - yv[i]) * DREC_SCALE;
        dxh[i] = drec * gg[i];
        p1 += dxh[i]; p2 += dxh[i] * xh[i];
    }
    #pragma unroll
    for (int o = 16; o; o >>= 1) {
        p1 += __shfl_xor_sync(0xffffffffu, p1, o);
        p2 += __shfl_xor_sync(0xffffffffu, p2, o);
    }
    const float s1 = p1 * (1.0f / CU), sx = p2 * (1.0f / CU);
    #pragma unroll
    for (int i = 0; i < 8; i++)
        dz[base + lane + i * 32] = roundtf(r * (dxh[i] - s1 - xh[i] * sx));
}

__global__ void contrib_k(const float* __restrict__ rec, float* __restrict__ out) {
    const int b = blockIdx.x, u = threadIdx.x;
    const float* p = rec + (size_t)b * (CL - 1) * CU + u;
    float s = 0.f;
    for (int t = 0; t < CL - 1; t++) s += p[(size_t)t * CU];
    out[(size_t)b * CU + u] = s * (1.0f / (CL - 1));
}

// ---------------- launch ----------------
extern "C" void kernel_launch(void* const* d_in, const int* in_sizes, int n_in,
                              void* d_out, int out_size) {
    const float* inputs = (const float*)d_in[0];
    const float* seq  = (const float*)d_in[2];
    const float* Wp   = (const float*)d_in[3];
    const float* bp   = (const float*)d_in[4];
    const float* Wphi = (const float*)d_in[5];
    const float* bphi = (const float*)d_in[6];
    const float* Wpsi = (const float*)d_in[7];
    const float* bpsi = (const float*)d_in[8];
    const float* W1   = (const float*)d_in[9];
    const float* b1   = (const float*)d_in[10];
    const float* W2   = (const float*)d_in[11];
    const float* b2   = (const float*)d_in[12];
    const float* Wg   = (const float*)d_in[13];
    const float* gb   = (const float*)d_in[14];
    const float* lng  = (const float*)d_in[15];
    const float* lnb  = (const float*)d_in[16];
    const float* Wh   = (const float*)d_in[17];
    const float* hb   = (const float*)d_in[18];

    float* out = (float*)d_out;
    float* buf_out = out + (size_t)CB * CU;

    cudaFuncSetAttribute(gemm_nn_tc,   cudaFuncAttributeMaxDynamicSharedMemorySize, GEMM_SMEM_BYTES);
    cudaFuncSetAttribute(gemm_nn_fast, cudaFuncAttributeMaxDynamicSharedMemorySize, FAST_SMEM_BYTES);
    cudaFuncSetAttribute(gemm_tn_fast, cudaFuncAttributeMaxDynamicSharedMemorySize, TN_SMEM_BYTES);

    float* S = nullptr;
    cudaGetSymbolAddress((void**)&S, g_scratch);
    float *PHI = S + O_PHI, *Z = S + O_Z, *REC = S + O_REC, *DZ = S + O_DZ;
    float *PRE = S + O_PRE, *H = S + O_H;
    float *DW1T = S + O_DW1T, *DW2T = S + O_DW2T, *DB1 = S + O_DB1, *DB2 = S + O_DB2;
    float *WpT = S + O_WPT, *WphiT = S + O_WPHIT, *W1T = S + O_W1T, *W2T = S + O_W2T;
    float *WpsiT = S + O_WPSIT, *WhT = S + O_WHT;
    float *WgR = S + O_WGR, *W2R = S + O_W2R, *WgT = S + O_WGT;
    float *COMBT = S + O_COMBT, *COMB = S + O_COMB, *GT = S + O_GT, *CDZ = S + O_CDZ;
    float *ZB = S + O_ZB;
    float *PROJ = S + O_PROJ, *PSI = S + O_PSI;
    float *HPSI = S + O_HPSI, *EPSI = S + O_EPSI, *CONTRIB = S + O_CONTRIB;
    float *XR = S + O_XR;

    // 0: all prep
    prep_all<<<PREP_BLOCKS, 256>>>(Wp, Wphi, W1, W2, Wg, Wpsi, Wh, b2, gb);

    // 1: proj = inputs @ Wp + bp
    gemm_nn_tc<<<dim3(1, CB / 128), 256, GEMM_SMEM_BYTES>>>(inputs, nullptr, WpT, nullptr, 0.f,
        bp, nullptr, 0.f, PROJ, nullptr, nullptr, 128, 128, 128, CU, 0, 1, 0, 0);

    // 2: shift buffer + rounded X (vectorized)
    shift_k<<<(CB * CL * 64) / 256, 256>>>((const float4*)seq, (const float4*)PROJ,
        (float4*)buf_out, (float4*)XR);

    // 3 (ncu-profiled): phi = XR @ Wphi + bphi (rounded output)
    gemm_nn_fast<<<dim3(CU / 128, CNR / 128), 128, FAST_SMEM_BYTES>>>(XR, WphiT,
        bphi, PHI, nullptr, nullptr, nullptr, CU, CU, CU, CU, 0, 1);

    // 4: COMB = W2 @ Wg [1024,256], rounded
    gemm_nn_tc<<<dim3(1, CH / 128), 256, GEMM_SMEM_BYTES>>>(W2R, nullptr, WgT, nullptr, 0.f,
        nullptr, nullptr, 0.f, COMB, nullptr, nullptr, CU, CU, CU, CU, 0, 0, 0, 1);

    // 5: COMBT = COMB^T
    transpose_k<<<dim3(CU / 32, CH / 32), dim3(256)>>>(COMB, COMBT, CH, CU);

    // pre = phi@W1+b1 ; H = gelu(pre) rounded, PRE := dgelu(pre)
    gemm_nn_fast<<<dim3(CH / 128, CNR / 128), 128, FAST_SMEM_BYTES>>>(PHI, W1T,
        b1, H, PRE, nullptr, nullptr, CU, CU, CU, CH, 1, 1);

    // z = H @ (W2@Wg) + (b2@Wg + gb)
    gemm_nn_fast<<<dim3(CU / 128, CNR / 128), 128, FAST_SMEM_BYTES>>>(H, COMBT,
        ZB, Z, nullptr, nullptr, nullptr, CH, CH, CH, CU, 0, 0);

    // rec = LN(z); dz = LN_bwd(...) rounded
    ln_fused_k<<<CNR / 8, 256>>>(Z, buf_out, lng, lnb, REC, DZ);

    // cdz = colsum(dz); db2 = Wg @ cdz
    colsum_k<<<dim3(CU / 32, 32), 256>>>(DZ, CDZ, CNR, CU, 2032);
    db2_k<<<1, 256>>>(Wg, CDZ, DB2);

    // GT = H^T @ dz  [1024,256]  (staged TN, 37 splits x 1760)
    gemm_tn_fast<<<dim3(CU / 128, CH / 128, 37), 128, TN_SMEM_BYTES>>>(
        H, DZ, GT, CNR, CH, CU, CU, 1760);

    // dW2T = Wg @ GT^T  [256,1024]
    gemm_nn_tc<<<dim3(CH / 256, CU / 128), 256, GEMM_SMEM_BYTES>>>(WgR, nullptr, GT, nullptr, 0.f,
        nullptr, nullptr, 0.f, DW2T, nullptr, nullptr, CU, CU, CU, CH, 0, 0, 1, 0);

    // dpre = (dz @ COMB^T) * stored-dgelu + db1 colsum; rounded, in-place over PRE
    gemm_nn_fast<<<dim3(CH / 128, CNR / 128), 128, FAST_SMEM_BYTES>>>(DZ, COMB,
        nullptr, PRE, nullptr, PRE, DB1, CU, CU, CU, CH, 2, 1);

    // dW1T = dpre^T @ phi  (staged TN)
    gemm_tn_fast<<<dim3(CU / 128, CH / 128, 37), 128, TN_SMEM_BYTES>>>(
        PRE, PHI, DW1T, CNR, CH, CU, CU, 1760);

    contrib_k<<<CB, 256>>>(REC, CONTRIB);

    // psi = proj @ Wpsi + bpsi  (rounded output)
    gemm_nn_tc<<<dim3(1, CB / 128), 256, GEMM_SMEM_BYTES>>>(PROJ, nullptr, WpsiT, nullptr, 0.f,
        bpsi, nullptr, 0.f, PSI, nullptr, nullptr, CU, CU, CU, CU, 0, 1, 0, 1);

    // hpsi = gelu(psi @ (W1 - lr dW1) + (b1 - lr db1))
    gemm_nn_tc<<<dim3(CH / 256, CB / 128), 256, GEMM_SMEM_BYTES>>>(PSI, nullptr, W1T, DW1T, -LR,
        b1, DB1, -LR, HPSI, nullptr, nullptr, CU, CU, CU, CH, 3, 0, 1, 1);

    // epsi = hpsi @ (W2 - lr dW2) + (b2 - lr db2)
    gemm_nn_tc<<<dim3(1, CB / 128), 256, GEMM_SMEM_BYTES>>>(HPSI, nullptr, W2T, DW2T, -LR,
        b2, DB2, -LR, EPSI, nullptr, nullptr, CH, CH, CH, CU, 0, 0, 1, 0);

    // out = (epsi + contrib) @ Wh + h_bias
    gemm_nn_tc<<<dim3(1, CB / 128), 256, GEMM_SMEM_BYTES>>>(EPSI, CONTRIB, WhT, nullptr, 0.f,
        hb, nullptr, 0.f, out, nullptr, nullptr, CU, CU, CU, CU, 0, 1, 0, 0);

    (void)in_sizes; (void)n_in; (void)out_size;
}